// round 1
// baseline (speedup 1.0000x reference)
#include <cuda_runtime.h>
#include <math.h>

#define S_LEN 1024
#define BATCH 8
#define BS_TOT 8192          // B*S
#define INNER 288
#define DIMX 192
#define NHQ 72
#define NHM 4
#define DHM 72

// ---------------- scratch (static __device__, no allocations) ----------------
__device__ float g_y [BS_TOT * 2 * INNER];  // proj_up output [8192,576]: x_m | z
__device__ float g_xa[BS_TOT * INNER];      // silu(conv(x_m))
__device__ float g_q [BS_TOT * INNER];
__device__ float g_k [BS_TOT * INNER];
__device__ float g_v [BS_TOT * INNER];
__device__ float g_ig[32 * S_LEN];          // [b*4+n][s]
__device__ float g_fg[32 * S_LEN];
__device__ float g_m [32 * S_LEN];          // ig - lfc
__device__ float g_Mx[32 * S_LEN];          // prefix max of m
__device__ float g_d0[32 * S_LEN];          // exp(-lfc - M)
__device__ float g_hs[BS_TOT * INNER];      // h_state (pre proj_down)

// ---------------- generic GEMM: C[M,N] = A[M,K] @ B[N,K]^T ----------------
// both row-major; BM=BN=64, BK=32, 256 threads, 4x4 micro-tile
__global__ void gemm_tn(const float* __restrict__ A, const float* __restrict__ Bm,
                        float* __restrict__ C, int M, int N, int K) {
    __shared__ float As[32][65];
    __shared__ float Bs[32][65];
    int r0 = blockIdx.y * 64, c0 = blockIdx.x * 64;
    int tid = threadIdx.x;
    int ty = tid >> 4, tx = tid & 15;
    float acc[4][4] = {};
    for (int k0 = 0; k0 < K; k0 += 32) {
        #pragma unroll
        for (int i = tid; i < 64 * 32; i += 256) {
            int r = i >> 5, kk = i & 31;
            As[kk][r] = A[(size_t)(r0 + r) * K + k0 + kk];
            Bs[kk][r] = Bm[(size_t)(c0 + r) * K + k0 + kk];
        }
        __syncthreads();
        #pragma unroll 8
        for (int kk = 0; kk < 32; kk++) {
            float a[4], b[4];
            #pragma unroll
            for (int i = 0; i < 4; i++) a[i] = As[kk][ty * 4 + i];
            #pragma unroll
            for (int j = 0; j < 4; j++) b[j] = Bs[kk][tx * 4 + j];
            #pragma unroll
            for (int i = 0; i < 4; i++)
                #pragma unroll
                for (int j = 0; j < 4; j++) acc[i][j] += a[i] * b[j];
        }
        __syncthreads();
    }
    #pragma unroll
    for (int i = 0; i < 4; i++) {
        float4 o = make_float4(acc[i][0], acc[i][1], acc[i][2], acc[i][3]);
        *(float4*)&C[(size_t)(r0 + ty * 4 + i) * N + c0 + tx * 4] = o;
    }
}

// ---------------- depthwise 3x3 conv (SAME) + SiLU ----------------
__global__ void conv_silu_kernel(const float* __restrict__ cw) {
    int idx = blockIdx.x * 256 + threadIdx.x;
    if (idx >= BS_TOT * INNER) return;
    int c  = idx % INNER;
    int bs = idx / INNER;
    int hw = bs & 1023, b = bs >> 10;
    int h = hw >> 5, w = hw & 31;
    float sum = 0.f;
    #pragma unroll
    for (int dh = -1; dh <= 1; dh++) {
        int hh = h + dh;
        if ((unsigned)hh >= 32u) continue;
        #pragma unroll
        for (int dw = -1; dw <= 1; dw++) {
            int ww = w + dw;
            if ((unsigned)ww >= 32u) continue;
            sum += g_y[(size_t)(b * S_LEN + hh * 32 + ww) * (2 * INNER) + c]
                 * cw[((dh + 1) * 3 + (dw + 1)) * INNER + c];
        }
    }
    g_xa[idx] = sum / (1.f + expf(-sum));   // silu
}

// ---------------- per-head 4x4 q/k/v transforms ----------------
__global__ void qkv_kernel(const float* __restrict__ qw, const float* __restrict__ kw,
                           const float* __restrict__ vw) {
    __shared__ float swq[NHQ * 16], swk[NHQ * 16], swv[NHQ * 16];
    for (int i = threadIdx.x; i < NHQ * 16; i += 256) {
        swq[i] = qw[i]; swk[i] = kw[i]; swv[i] = vw[i];
    }
    __syncthreads();
    int gid = blockIdx.x * 256 + threadIdx.x;
    if (gid >= BS_TOT * NHQ) return;
    int h = gid % NHQ, bs = gid / NHQ;
    float4 xa = *(const float4*)&g_xa[(size_t)bs * INNER + h * 4];
    float4 xm = *(const float4*)&g_y[(size_t)bs * (2 * INNER) + h * 4];
    float qo[4], ko[4], vo[4];
    #pragma unroll
    for (int o = 0; o < 4; o++) {
        const float* wq = &swq[h * 16 + o * 4];
        const float* wk = &swk[h * 16 + o * 4];
        const float* wv = &swv[h * 16 + o * 4];
        qo[o] = xa.x * wq[0] + xa.y * wq[1] + xa.z * wq[2] + xa.w * wq[3];
        ko[o] = xa.x * wk[0] + xa.y * wk[1] + xa.z * wk[2] + xa.w * wk[3];
        vo[o] = xm.x * wv[0] + xm.y * wv[1] + xm.z * wv[2] + xm.w * wv[3];
    }
    *(float4*)&g_q[(size_t)bs * INNER + h * 4] = make_float4(qo[0], qo[1], qo[2], qo[3]);
    *(float4*)&g_k[(size_t)bs * INNER + h * 4] = make_float4(ko[0], ko[1], ko[2], ko[3]);
    *(float4*)&g_v[(size_t)bs * INNER + h * 4] = make_float4(vo[0], vo[1], vo[2], vo[3]);
}

// ---------------- gate projections: ig/fg [B,4,S] ----------------
__global__ void gates_kernel(const float* __restrict__ igw, const float* __restrict__ igb,
                             const float* __restrict__ fgw, const float* __restrict__ fgb) {
    __shared__ float sig[NHM * 864], sfg[NHM * 864];
    for (int i = threadIdx.x; i < NHM * 864; i += 256) { sig[i] = igw[i]; sfg[i] = fgw[i]; }
    __syncthreads();
    int warp = threadIdx.x >> 5, lane = threadIdx.x & 31;
    int bs = blockIdx.x * 8 + warp;
    float ai[4] = {0, 0, 0, 0}, af[4] = {0, 0, 0, 0};
    for (int c = lane; c < 864; c += 32) {
        float g = (c < 288) ? g_q[(size_t)bs * 288 + c]
                 : (c < 576) ? g_k[(size_t)bs * 288 + c - 288]
                             : g_v[(size_t)bs * 288 + c - 576];
        #pragma unroll
        for (int n = 0; n < 4; n++) {
            ai[n] += g * sig[n * 864 + c];
            af[n] += g * sfg[n * 864 + c];
        }
    }
    #pragma unroll
    for (int off = 16; off; off >>= 1) {
        #pragma unroll
        for (int n = 0; n < 4; n++) {
            ai[n] += __shfl_down_sync(0xffffffffu, ai[n], off);
            af[n] += __shfl_down_sync(0xffffffffu, af[n], off);
        }
    }
    if (lane == 0) {
        int b = bs >> 10, s = bs & 1023;
        #pragma unroll
        for (int n = 0; n < 4; n++) {
            g_ig[(size_t)(b * 4 + n) * S_LEN + s] = ai[n] + igb[n];
            g_fg[(size_t)(b * 4 + n) * S_LEN + s] = af[n] + fgb[n];
        }
    }
}

// ---------------- scan: lfc (cumsum log_sigmoid fg), m, prefix-max M, d0 ----------------
__global__ void scan_kernel() {
    __shared__ float buf[S_LEN];
    int t = threadIdx.x;
    int base = blockIdx.x * S_LEN;
    float fgv = g_fg[base + t];
    float lf = fminf(fgv, 0.f) - log1pf(expf(-fabsf(fgv)));   // log_sigmoid
    buf[t] = lf;
    __syncthreads();
    #pragma unroll
    for (int off = 1; off < S_LEN; off <<= 1) {
        float v = buf[t];
        if (t >= off) v += buf[t - off];
        __syncthreads();
        buf[t] = v;
        __syncthreads();
    }
    float lfc = buf[t];
    float m = g_ig[base + t] - lfc;
    __syncthreads();
    buf[t] = m;
    __syncthreads();
    #pragma unroll
    for (int off = 1; off < S_LEN; off <<= 1) {
        float v = buf[t];
        if (t >= off) v = fmaxf(v, buf[t - off]);
        __syncthreads();
        buf[t] = v;
        __syncthreads();
    }
    float Mv = buf[t];
    g_m [base + t] = m;
    g_Mx[base + t] = Mv;
    g_d0[base + t] = expf(-lfc - Mv);
}

// ---------------- mLSTM attention + fused LN/skip/silu(z) ----------------
// grid: (16 row-tiles, 32 bn), 256 threads, ~81KB dynamic smem
__global__ void attn_kernel(const float* __restrict__ normw, const float* __restrict__ skipw) {
    extern __shared__ float sm[];
    float* qs     = sm;                 // 64*76
    float* ks     = qs + 64 * 76;       // 64*76
    float* vs     = ks + 64 * 76;       // 64*76
    float* Ps     = vs + 64 * 76;       // 64*68
    float* rsp    = Ps + 64 * 68;       // 64*16
    float* rowsum = rsp + 64 * 16;      // 64
    float* wm     = rowsum + 64;        // 64
    float* wr     = wm + 64;            // 64
    float* d0s    = wr + 64;            // 64

    int R  = gridDim.x - 1 - blockIdx.x;   // heavy blocks first
    int bn = blockIdx.y;
    int b = bn >> 2, n = bn & 3;
    int S0 = R * 64;
    int tid = threadIdx.x;

    for (int i = tid; i < 64 * 72; i += 256) {
        int r = i / 72, d = i % 72;
        qs[r * 76 + d] = g_q[(size_t)(b * S_LEN + S0 + r) * INNER + n * 72 + d];
    }
    if (tid < 64) {
        float Mv = g_Mx[(size_t)bn * S_LEN + S0 + tid];
        wr[tid]  = expf(-Mv);
        d0s[tid] = g_d0[(size_t)bn * S_LEN + S0 + tid];
        rowsum[tid] = 0.f;
    }

    int ty = tid >> 4, tx = tid & 15;
    int warp = tid >> 5, lane = tid & 31;
    float acc[8][3];
    #pragma unroll
    for (int i = 0; i < 8; i++) { acc[i][0] = 0; acc[i][1] = 0; acc[i][2] = 0; }
    const float scale = 0.11785113019775793f;  // 1/sqrt(72)

    for (int ct = 0; ct <= R; ct++) {
        __syncthreads();   // prev PhaseB done before overwriting tiles
        int T0 = ct * 64;
        for (int i = tid; i < 64 * 72; i += 256) {
            int r = i / 72, d = i % 72;
            ks[r * 76 + d] = g_k[(size_t)(b * S_LEN + T0 + r) * INNER + n * 72 + d];
            vs[r * 76 + d] = g_v[(size_t)(b * S_LEN + T0 + r) * INNER + n * 72 + d];
        }
        if (tid < 64) wm[tid] = expf(g_m[(size_t)bn * S_LEN + T0 + tid]);
        __syncthreads();

        // Phase A: P = (q k^T * scale) * Dm, + rowsum partials
        float pacc[4][4] = {};
        #pragma unroll 8
        for (int kk = 0; kk < 72; kk++) {
            float a[4], bq[4];
            #pragma unroll
            for (int i = 0; i < 4; i++) a[i] = qs[(ty * 4 + i) * 76 + kk];
            #pragma unroll
            for (int j = 0; j < 4; j++) bq[j] = ks[(tx * 4 + j) * 76 + kk];
            #pragma unroll
            for (int i = 0; i < 4; i++)
                #pragma unroll
                for (int j = 0; j < 4; j++) pacc[i][j] += a[i] * bq[j];
        }
        bool diag = (ct == R);
        #pragma unroll
        for (int i = 0; i < 4; i++) {
            int r = ty * 4 + i;
            float wrow = wr[r] * scale;
            float rs = 0.f;
            #pragma unroll
            for (int j = 0; j < 4; j++) {
                int c = tx * 4 + j;
                float v = (!diag || c <= r) ? pacc[i][j] * wrow * wm[c] : 0.f;
                Ps[r * 68 + c] = v;
                rs += v;
            }
            rsp[r * 16 + tx] = rs;
        }
        __syncthreads();

        if (tid < 64) {
            float t = 0.f;
            #pragma unroll
            for (int x = 0; x < 16; x++) t += rsp[tid * 16 + x];
            rowsum[tid] += t;
        }

        // Phase B: acc += P @ v (warp owns 8 rows; lane owns d, d+32, d+64(lane<8))
        int r0 = warp * 8;
        #pragma unroll 2
        for (int k = 0; k < 64; k++) {
            float v0 = vs[k * 76 + lane];
            float v1 = vs[k * 76 + 32 + lane];
            float v2 = (lane < 8) ? vs[k * 76 + 64 + lane] : 0.f;
            #pragma unroll
            for (int r8 = 0; r8 < 8; r8++) {
                float p = Ps[(r0 + r8) * 68 + k];
                acc[r8][0] += p * v0;
                acc[r8][1] += p * v1;
                acc[r8][2] += p * v2;
            }
        }
    }
    __syncthreads();

    // Epilogue: normalizer division + per-row LN + skip + silu(z)
    int r0 = warp * 8;
    float nw0 = normw[n * 72 + lane];
    float sk0 = skipw[n * 72 + lane];
    float nw1 = normw[n * 72 + 32 + lane];
    float sk1 = skipw[n * 72 + 32 + lane];
    float nw2 = 0.f, sk2 = 0.f;
    if (lane < 8) { nw2 = normw[n * 72 + 64 + lane]; sk2 = skipw[n * 72 + 64 + lane]; }

    #pragma unroll
    for (int r8 = 0; r8 < 8; r8++) {
        int r = r0 + r8;
        float nrm = fmaxf(fabsf(rowsum[r]), d0s[r]);
        float inv = 1.f / (nrm + 1e-6f);
        float h0 = acc[r8][0] * inv;
        float h1 = acc[r8][1] * inv;
        float h2 = acc[r8][2] * inv;   // 0 for lane>=8 (v2 was 0)
        float psum = h0 + h1 + ((lane < 8) ? h2 : 0.f);
        #pragma unroll
        for (int off = 16; off; off >>= 1) psum += __shfl_xor_sync(0xffffffffu, psum, off);
        float mean = psum * (1.f / 72.f);
        float dv0 = h0 - mean, dv1 = h1 - mean, dv2 = h2 - mean;
        float pss = dv0 * dv0 + dv1 * dv1 + ((lane < 8) ? dv2 * dv2 : 0.f);
        #pragma unroll
        for (int off = 16; off; off >>= 1) pss += __shfl_xor_sync(0xffffffffu, pss, off);
        float rstd = rsqrtf(pss * (1.f / 72.f) + 1e-5f);

        size_t row  = (size_t)(b * S_LEN + S0 + r) * INNER;
        size_t zrow = (size_t)(b * S_LEN + S0 + r) * (2 * INNER) + INNER;
        {
            int c = n * 72 + lane;
            float z = g_y[zrow + c];
            float val = dv0 * rstd * nw0 + sk0 * g_xa[row + c];
            g_hs[row + c] = val * (z / (1.f + expf(-z)));
        }
        {
            int c = n * 72 + 32 + lane;
            float z = g_y[zrow + c];
            float val = dv1 * rstd * nw1 + sk1 * g_xa[row + c];
            g_hs[row + c] = val * (z / (1.f + expf(-z)));
        }
        if (lane < 8) {
            int c = n * 72 + 64 + lane;
            float z = g_y[zrow + c];
            float val = dv2 * rstd * nw2 + sk2 * g_xa[row + c];
            g_hs[row + c] = val * (z / (1.f + expf(-z)));
        }
    }
}

// ---------------- launch ----------------
extern "C" void kernel_launch(void* const* d_in, const int* in_sizes, int n_in,
                              void* d_out, int out_size) {
    const float* x           = (const float*)d_in[0];
    const float* proj_up_w   = (const float*)d_in[1];
    const float* q_w         = (const float*)d_in[2];
    const float* k_w         = (const float*)d_in[3];
    const float* v_w         = (const float*)d_in[4];
    const float* conv_w      = (const float*)d_in[5];
    const float* ig_w        = (const float*)d_in[6];
    const float* ig_b        = (const float*)d_in[7];
    const float* fg_w        = (const float*)d_in[8];
    const float* fg_b        = (const float*)d_in[9];
    const float* norm_w      = (const float*)d_in[10];
    const float* skip        = (const float*)d_in[11];
    const float* proj_down_w = (const float*)d_in[12];
    float* out = (float*)d_out;

    float *py, *phs;
    cudaGetSymbolAddress((void**)&py,  g_y);
    cudaGetSymbolAddress((void**)&phs, g_hs);

    // 1) proj_up: g_y[8192,576] = x[8192,192] @ W_up^T
    gemm_tn<<<dim3(576 / 64, BS_TOT / 64), 256>>>(x, proj_up_w, py, BS_TOT, 2 * INNER, DIMX);

    // 2) depthwise conv 3x3 + silu -> g_xa
    conv_silu_kernel<<<(BS_TOT * INNER + 255) / 256, 256>>>(conv_w);

    // 3) headwise q,k,v
    qkv_kernel<<<(BS_TOT * NHQ + 255) / 256, 256>>>(q_w, k_w, v_w);

    // 4) gates
    gates_kernel<<<BS_TOT / 8, 256>>>(ig_w, ig_b, fg_w, fg_b);

    // 5) scan per (b,n)
    scan_kernel<<<32, S_LEN>>>();

    // 6) attention + LN + skip + silu(z) -> g_hs
    size_t smem = (size_t)(3 * 64 * 76 + 64 * 68 + 64 * 16 + 4 * 64) * sizeof(float);
    cudaFuncSetAttribute(attn_kernel, cudaFuncAttributeMaxDynamicSharedMemorySize, (int)smem);
    attn_kernel<<<dim3(16, 32), 256, smem>>>(norm_w, skip);

    // 7) proj_down: out[8192,192] = g_hs @ W_down^T
    gemm_tn<<<dim3(DIMX / 64, BS_TOT / 64), 256>>>(phs, proj_down_w, out, BS_TOT, DIMX, INNER);
}

// round 2
// speedup vs baseline: 2.6873x; 2.6873x over previous
#include <cuda_runtime.h>
#include <math.h>
#include <stdint.h>

#define S_LEN 1024
#define BATCH 8
#define BS_TOT 8192          // B*S
#define INNER 288
#define DIMX 192
#define NHQ 72
#define NHM 4
#define DHM 72

// ---------------- scratch (static __device__, no allocations) ----------------
__device__ float g_y [BS_TOT * 2 * INNER];  // proj_up output [8192,576]: x_m | z
__device__ float g_xa[BS_TOT * INNER];      // silu(conv(x_m))
__device__ float g_q [BS_TOT * INNER];
__device__ float g_k [BS_TOT * INNER];
__device__ float g_v [BS_TOT * INNER];
__device__ float g_ig[32 * S_LEN];          // [b*4+n][s]
__device__ float g_fg[32 * S_LEN];
__device__ float g_m [32 * S_LEN];          // ig - lfc
__device__ float g_Mx[32 * S_LEN];          // prefix max of m
__device__ float g_d0[32 * S_LEN];          // exp(-lfc - M)
__device__ float g_hs[BS_TOT * INNER];      // h_state (pre proj_down)

// ---------------- tf32 helpers ----------------
__device__ __forceinline__ float to_tf32(float x) {
    float y;
    asm("cvt.rna.tf32.f32 %0, %1;" : "=f"(y) : "f"(x));
    return y;
}

__device__ __forceinline__ void mma_tf32(float c[4], uint32_t a0, uint32_t a1,
                                         uint32_t a2, uint32_t a3,
                                         uint32_t b0, uint32_t b1) {
    asm volatile(
        "mma.sync.aligned.m16n8k8.row.col.f32.tf32.tf32.f32 "
        "{%0,%1,%2,%3}, {%4,%5,%6,%7}, {%8,%9}, {%0,%1,%2,%3};"
        : "+f"(c[0]), "+f"(c[1]), "+f"(c[2]), "+f"(c[3])
        : "r"(a0), "r"(a1), "r"(a2), "r"(a3), "r"(b0), "r"(b1));
}

// ---------------- tf32 GEMM: C[M,N] = A[M,K] @ B[N,K]^T ----------------
// BM=128, BN=64, BK=16, 256 threads, warps 2(M)x4(N), warp tile 64x16
__global__ void __launch_bounds__(256) gemm_tf32(
        const float* __restrict__ A, const float* __restrict__ Bm,
        float* __restrict__ C, int M, int N, int K) {
    __shared__ float As[128][20];
    __shared__ float Bs[64][20];
    int r0 = blockIdx.y * 128, c0 = blockIdx.x * 64;
    int tid = threadIdx.x, lane = tid & 31, warp = tid >> 5;
    int wm = warp >> 2, wn = warp & 3;
    int mb = wm * 64, nb = wn * 16;
    int ln4 = lane >> 2, q4 = lane & 3;
    float acc[4][2][4] = {};

    for (int k0 = 0; k0 < K; k0 += 16) {
        #pragma unroll
        for (int i = tid; i < 512; i += 256) {
            int r = i >> 2, qq = (i & 3) * 4;
            float4 v = *(const float4*)&A[(size_t)(r0 + r) * K + k0 + qq];
            As[r][qq + 0] = to_tf32(v.x); As[r][qq + 1] = to_tf32(v.y);
            As[r][qq + 2] = to_tf32(v.z); As[r][qq + 3] = to_tf32(v.w);
        }
        {
            int r = tid >> 2, qq = (tid & 3) * 4;
            float4 v = *(const float4*)&Bm[(size_t)(c0 + r) * K + k0 + qq];
            Bs[r][qq + 0] = to_tf32(v.x); Bs[r][qq + 1] = to_tf32(v.y);
            Bs[r][qq + 2] = to_tf32(v.z); Bs[r][qq + 3] = to_tf32(v.w);
        }
        __syncthreads();
        #pragma unroll
        for (int ks = 0; ks < 16; ks += 8) {
            uint32_t a[4][4];
            #pragma unroll
            for (int mf = 0; mf < 4; mf++) {
                int m0 = mb + mf * 16;
                a[mf][0] = __float_as_uint(As[m0 + ln4][ks + q4]);
                a[mf][1] = __float_as_uint(As[m0 + 8 + ln4][ks + q4]);
                a[mf][2] = __float_as_uint(As[m0 + ln4][ks + 4 + q4]);
                a[mf][3] = __float_as_uint(As[m0 + 8 + ln4][ks + 4 + q4]);
            }
            #pragma unroll
            for (int nf = 0; nf < 2; nf++) {
                int n0 = nb + nf * 8;
                uint32_t b0 = __float_as_uint(Bs[n0 + ln4][ks + q4]);
                uint32_t b1 = __float_as_uint(Bs[n0 + ln4][ks + 4 + q4]);
                #pragma unroll
                for (int mf = 0; mf < 4; mf++)
                    mma_tf32(acc[mf][nf], a[mf][0], a[mf][1], a[mf][2], a[mf][3], b0, b1);
            }
        }
        __syncthreads();
    }
    #pragma unroll
    for (int mf = 0; mf < 4; mf++)
        #pragma unroll
        for (int nf = 0; nf < 2; nf++) {
            int row = r0 + mb + mf * 16 + ln4;
            int col = c0 + nb + nf * 8 + 2 * q4;
            C[(size_t)row * N + col]       = acc[mf][nf][0];
            C[(size_t)row * N + col + 1]   = acc[mf][nf][1];
            C[(size_t)(row + 8) * N + col]     = acc[mf][nf][2];
            C[(size_t)(row + 8) * N + col + 1] = acc[mf][nf][3];
        }
}

// ---------------- depthwise 3x3 conv (SAME) + SiLU ----------------
__global__ void conv_silu_kernel(const float* __restrict__ cw) {
    int idx = blockIdx.x * 256 + threadIdx.x;
    if (idx >= BS_TOT * INNER) return;
    int c  = idx % INNER;
    int bs = idx / INNER;
    int hw = bs & 1023, b = bs >> 10;
    int h = hw >> 5, w = hw & 31;
    float sum = 0.f;
    #pragma unroll
    for (int dh = -1; dh <= 1; dh++) {
        int hh = h + dh;
        if ((unsigned)hh >= 32u) continue;
        #pragma unroll
        for (int dw = -1; dw <= 1; dw++) {
            int ww = w + dw;
            if ((unsigned)ww >= 32u) continue;
            sum += g_y[(size_t)(b * S_LEN + hh * 32 + ww) * (2 * INNER) + c]
                 * cw[((dh + 1) * 3 + (dw + 1)) * INNER + c];
        }
    }
    g_xa[idx] = sum / (1.f + expf(-sum));   // silu
}

// ---------------- per-head 4x4 q/k/v transforms ----------------
__global__ void qkv_kernel(const float* __restrict__ qw, const float* __restrict__ kw,
                           const float* __restrict__ vw) {
    __shared__ float swq[NHQ * 16], swk[NHQ * 16], swv[NHQ * 16];
    for (int i = threadIdx.x; i < NHQ * 16; i += 256) {
        swq[i] = qw[i]; swk[i] = kw[i]; swv[i] = vw[i];
    }
    __syncthreads();
    int gid = blockIdx.x * 256 + threadIdx.x;
    if (gid >= BS_TOT * NHQ) return;
    int h = gid % NHQ, bs = gid / NHQ;
    float4 xa = *(const float4*)&g_xa[(size_t)bs * INNER + h * 4];
    float4 xm = *(const float4*)&g_y[(size_t)bs * (2 * INNER) + h * 4];
    float qo[4], ko[4], vo[4];
    #pragma unroll
    for (int o = 0; o < 4; o++) {
        const float* wq = &swq[h * 16 + o * 4];
        const float* wk = &swk[h * 16 + o * 4];
        const float* wv = &swv[h * 16 + o * 4];
        qo[o] = xa.x * wq[0] + xa.y * wq[1] + xa.z * wq[2] + xa.w * wq[3];
        ko[o] = xa.x * wk[0] + xa.y * wk[1] + xa.z * wk[2] + xa.w * wk[3];
        vo[o] = xm.x * wv[0] + xm.y * wv[1] + xm.z * wv[2] + xm.w * wv[3];
    }
    *(float4*)&g_q[(size_t)bs * INNER + h * 4] = make_float4(qo[0], qo[1], qo[2], qo[3]);
    *(float4*)&g_k[(size_t)bs * INNER + h * 4] = make_float4(ko[0], ko[1], ko[2], ko[3]);
    *(float4*)&g_v[(size_t)bs * INNER + h * 4] = make_float4(vo[0], vo[1], vo[2], vo[3]);
}

// ---------------- gate projections: ig/fg [B,4,S] ----------------
__global__ void gates_kernel(const float* __restrict__ igw, const float* __restrict__ igb,
                             const float* __restrict__ fgw, const float* __restrict__ fgb) {
    __shared__ float sig[NHM * 864], sfg[NHM * 864];
    for (int i = threadIdx.x; i < NHM * 864; i += 256) { sig[i] = igw[i]; sfg[i] = fgw[i]; }
    __syncthreads();
    int warp = threadIdx.x >> 5, lane = threadIdx.x & 31;
    int bs = blockIdx.x * 8 + warp;
    float ai[4] = {0, 0, 0, 0}, af[4] = {0, 0, 0, 0};
    for (int c = lane; c < 864; c += 32) {
        float g = (c < 288) ? g_q[(size_t)bs * 288 + c]
                 : (c < 576) ? g_k[(size_t)bs * 288 + c - 288]
                             : g_v[(size_t)bs * 288 + c - 576];
        #pragma unroll
        for (int n = 0; n < 4; n++) {
            ai[n] += g * sig[n * 864 + c];
            af[n] += g * sfg[n * 864 + c];
        }
    }
    #pragma unroll
    for (int off = 16; off; off >>= 1) {
        #pragma unroll
        for (int n = 0; n < 4; n++) {
            ai[n] += __shfl_down_sync(0xffffffffu, ai[n], off);
            af[n] += __shfl_down_sync(0xffffffffu, af[n], off);
        }
    }
    if (lane == 0) {
        int b = bs >> 10, s = bs & 1023;
        #pragma unroll
        for (int n = 0; n < 4; n++) {
            g_ig[(size_t)(b * 4 + n) * S_LEN + s] = ai[n] + igb[n];
            g_fg[(size_t)(b * 4 + n) * S_LEN + s] = af[n] + fgb[n];
        }
    }
}

// ---------------- scan: lfc (cumsum log_sigmoid fg), m, prefix-max M, d0 ----------------
__global__ void scan_kernel() {
    __shared__ float wbuf[32];
    int t = threadIdx.x, lane = t & 31, wid = t >> 5;
    int base = blockIdx.x * S_LEN;
    float fgv = g_fg[base + t];
    float lf = fminf(fgv, 0.f) - log1pf(expf(-fabsf(fgv)));   // log_sigmoid
    // inclusive sum scan
    float v = lf;
    #pragma unroll
    for (int o = 1; o < 32; o <<= 1) {
        float u = __shfl_up_sync(0xffffffffu, v, o);
        if (lane >= o) v += u;
    }
    if (lane == 31) wbuf[wid] = v;
    __syncthreads();
    if (wid == 0) {
        float s = wbuf[lane];
        #pragma unroll
        for (int o = 1; o < 32; o <<= 1) {
            float u = __shfl_up_sync(0xffffffffu, s, o);
            if (lane >= o) s += u;
        }
        wbuf[lane] = s;
    }
    __syncthreads();
    float lfc = v + (wid ? wbuf[wid - 1] : 0.f);
    float m = g_ig[base + t] - lfc;
    __syncthreads();
    // inclusive max scan
    float mx = m;
    #pragma unroll
    for (int o = 1; o < 32; o <<= 1) {
        float u = __shfl_up_sync(0xffffffffu, mx, o);
        if (lane >= o) mx = fmaxf(mx, u);
    }
    if (lane == 31) wbuf[wid] = mx;
    __syncthreads();
    if (wid == 0) {
        float s = wbuf[lane];
        #pragma unroll
        for (int o = 1; o < 32; o <<= 1) {
            float u = __shfl_up_sync(0xffffffffu, s, o);
            if (lane >= o) s = fmaxf(s, u);
        }
        wbuf[lane] = s;
    }
    __syncthreads();
    float Mv = wid ? fmaxf(mx, wbuf[wid - 1]) : mx;
    g_m [base + t] = m;
    g_Mx[base + t] = Mv;
    g_d0[base + t] = expf(-lfc - Mv);
}

// ---------------- mLSTM attention (tf32 mma) + fused LN/skip/silu(z) ----------------
// grid: (16 row-tiles heavy-first, 32 bn), 256 threads
// smem: Qs[64][76] | Ks[64][76] | Vs[64][88] | Ps[64][68] | wms[64] wr[64] d0s[64] invs[64] | rsA[2][64]
__global__ void __launch_bounds__(256) attn_kernel(const float* __restrict__ normw,
                                                   const float* __restrict__ skipw) {
    extern __shared__ float sm[];
    float* Qs  = sm;                  // 64*76 (later aliased as O output)
    float* Ks  = Qs + 64 * 76;        // 64*76
    float* Vs  = Ks + 64 * 76;        // 64*88 (cols 72..79 zero pad)
    float* Ps  = Vs + 64 * 88;        // 64*68
    float* wms = Ps + 64 * 68;        // 64
    float* wr  = wms + 64;            // 64
    float* d0s = wr + 64;             // 64
    float* invs = d0s + 64;           // 64
    float* rsA = invs + 64;           // 2*64

    int R  = gridDim.x - 1 - blockIdx.x;   // heavy blocks first
    int bn = blockIdx.y;
    int b = bn >> 2, n = bn & 3;
    int S0 = R * 64;
    int tid = threadIdx.x, lane = tid & 31, warp = tid >> 5;
    int wm = warp >> 1, wn = warp & 1;     // 4(M) x 2(N)
    int ln4 = lane >> 2, q4 = lane & 3;
    int r0 = wm * 16;
    const float scale = 0.11785113019775793f;  // 1/sqrt(72)

    // preload Q tile (as tf32)
    for (int i = tid; i < 64 * 18; i += 256) {
        int r = i / 18, j = (i % 18) * 4;
        float4 v = *(const float4*)&g_q[(size_t)(b * S_LEN + S0 + r) * INNER + n * 72 + j];
        Qs[r * 76 + j + 0] = to_tf32(v.x); Qs[r * 76 + j + 1] = to_tf32(v.y);
        Qs[r * 76 + j + 2] = to_tf32(v.z); Qs[r * 76 + j + 3] = to_tf32(v.w);
    }
    if (tid < 64) {
        float Mv = g_Mx[(size_t)bn * S_LEN + S0 + tid];
        wr[tid]  = expf(-Mv);
        d0s[tid] = g_d0[(size_t)bn * S_LEN + S0 + tid];
        rsA[tid] = 0.f; rsA[64 + tid] = 0.f;
    }
    // zero V pad columns (written once, never overwritten)
    for (int i = tid; i < 64 * 8; i += 256) {
        int r = i >> 3, c = 72 + (i & 7);
        Vs[r * 88 + c] = 0.f;
    }

    float o[5][4] = {};   // persistent PV accumulators (16x40 per warp)

    for (int ct = 0; ct <= R; ct++) {
        __syncthreads();   // prev Phase B done before overwriting K/V/wm
        int T0 = ct * 64;
        for (int i = tid; i < 64 * 18; i += 256) {
            int r = i / 18, j = (i % 18) * 4;
            size_t gb = (size_t)(b * S_LEN + T0 + r) * INNER + n * 72 + j;
            float4 kv = *(const float4*)&g_k[gb];
            float4 vv = *(const float4*)&g_v[gb];
            Ks[r * 76 + j + 0] = to_tf32(kv.x); Ks[r * 76 + j + 1] = to_tf32(kv.y);
            Ks[r * 76 + j + 2] = to_tf32(kv.z); Ks[r * 76 + j + 3] = to_tf32(kv.w);
            Vs[r * 88 + j + 0] = to_tf32(vv.x); Vs[r * 88 + j + 1] = to_tf32(vv.y);
            Vs[r * 88 + j + 2] = to_tf32(vv.z); Vs[r * 88 + j + 3] = to_tf32(vv.w);
        }
        if (tid < 64) wms[tid] = expf(g_m[(size_t)bn * S_LEN + T0 + tid]);
        __syncthreads();

        // ---- Phase A: P = Q @ K^T  (64x64x72) ----
        float pc[4][4] = {};
        #pragma unroll
        for (int ks = 0; ks < 72; ks += 8) {
            uint32_t a0 = __float_as_uint(Qs[(r0 + ln4) * 76 + ks + q4]);
            uint32_t a1 = __float_as_uint(Qs[(r0 + 8 + ln4) * 76 + ks + q4]);
            uint32_t a2 = __float_as_uint(Qs[(r0 + ln4) * 76 + ks + 4 + q4]);
            uint32_t a3 = __float_as_uint(Qs[(r0 + 8 + ln4) * 76 + ks + 4 + q4]);
            #pragma unroll
            for (int nf = 0; nf < 4; nf++) {
                int c0 = wn * 32 + nf * 8;
                uint32_t b0 = __float_as_uint(Ks[(c0 + ln4) * 76 + ks + q4]);
                uint32_t b1 = __float_as_uint(Ks[(c0 + ln4) * 76 + ks + 4 + q4]);
                mma_tf32(pc[nf], a0, a1, a2, a3, b0, b1);
            }
        }
        // weight, mask, tf32-round, store to Ps, accumulate rowsums
        bool diag = (ct == R);
        int rr = r0 + ln4;
        float w0 = wr[rr] * scale, w1 = wr[rr + 8] * scale;
        float s_r = 0.f, s_r8 = 0.f;
        #pragma unroll
        for (int nf = 0; nf < 4; nf++) {
            int cbase = wn * 32 + nf * 8 + 2 * q4;
            #pragma unroll
            for (int e = 0; e < 2; e++) {
                int c = cbase + e;
                float wc = wms[c];
                float v0 = pc[nf][e]     * w0 * wc;
                float v1 = pc[nf][2 + e] * w1 * wc;
                if (diag && c > rr)     v0 = 0.f;
                if (diag && c > rr + 8) v1 = 0.f;
                v0 = to_tf32(v0); v1 = to_tf32(v1);
                Ps[rr * 68 + c] = v0;
                Ps[(rr + 8) * 68 + c] = v1;
                s_r += v0; s_r8 += v1;
            }
        }
        s_r  += __shfl_xor_sync(0xffffffffu, s_r, 1);
        s_r  += __shfl_xor_sync(0xffffffffu, s_r, 2);
        s_r8 += __shfl_xor_sync(0xffffffffu, s_r8, 1);
        s_r8 += __shfl_xor_sync(0xffffffffu, s_r8, 2);
        if (q4 == 0) {
            rsA[wn * 64 + rr]     += s_r;
            rsA[wn * 64 + rr + 8] += s_r8;
        }
        __syncthreads();

        // ---- Phase B: O += P @ V  (64x80x64) ----
        #pragma unroll
        for (int ks = 0; ks < 64; ks += 8) {
            uint32_t a0 = __float_as_uint(Ps[(r0 + ln4) * 68 + ks + q4]);
            uint32_t a1 = __float_as_uint(Ps[(r0 + 8 + ln4) * 68 + ks + q4]);
            uint32_t a2 = __float_as_uint(Ps[(r0 + ln4) * 68 + ks + 4 + q4]);
            uint32_t a3 = __float_as_uint(Ps[(r0 + 8 + ln4) * 68 + ks + 4 + q4]);
            #pragma unroll
            for (int nf = 0; nf < 5; nf++) {
                int c0 = wn * 40 + nf * 8;
                uint32_t b0 = __float_as_uint(Vs[(ks + q4) * 88 + c0 + ln4]);
                uint32_t b1 = __float_as_uint(Vs[(ks + 4 + q4) * 88 + c0 + ln4]);
                mma_tf32(o[nf], a0, a1, a2, a3, b0, b1);
            }
        }
    }
    __syncthreads();

    // normalizer
    if (tid < 64) {
        float rs = rsA[tid] + rsA[64 + tid];
        float nrm = fmaxf(fabsf(rs), d0s[tid]);
        invs[tid] = 1.f / (nrm + 1e-6f);
    }
    __syncthreads();

    // write normalized O into Qs (reused as O buffer, stride 76, cols 0..71)
    {
        float i0 = invs[r0 + ln4], i1 = invs[r0 + 8 + ln4];
        #pragma unroll
        for (int nf = 0; nf < 5; nf++) {
            int cb = wn * 40 + nf * 8 + 2 * q4;
            if (cb < 72) {
                Qs[(r0 + ln4) * 76 + cb]         = o[nf][0] * i0;
                Qs[(r0 + ln4) * 76 + cb + 1]     = o[nf][1] * i0;
                Qs[(r0 + 8 + ln4) * 76 + cb]     = o[nf][2] * i1;
                Qs[(r0 + 8 + ln4) * 76 + cb + 1] = o[nf][3] * i1;
            }
        }
    }
    __syncthreads();

    // Epilogue: per-row LN + skip + silu(z)  (warp owns 8 rows)
    int re0 = warp * 8;
    float nw0 = normw[n * 72 + lane];
    float sk0 = skipw[n * 72 + lane];
    float nw1 = normw[n * 72 + 32 + lane];
    float sk1 = skipw[n * 72 + 32 + lane];
    float nw2 = 0.f, sk2 = 0.f;
    if (lane < 8) { nw2 = normw[n * 72 + 64 + lane]; sk2 = skipw[n * 72 + 64 + lane]; }

    #pragma unroll
    for (int r8 = 0; r8 < 8; r8++) {
        int r = re0 + r8;
        float h0 = Qs[r * 76 + lane];
        float h1 = Qs[r * 76 + 32 + lane];
        float h2 = (lane < 8) ? Qs[r * 76 + 64 + lane] : 0.f;
        float psum = h0 + h1 + h2;
        #pragma unroll
        for (int off = 16; off; off >>= 1) psum += __shfl_xor_sync(0xffffffffu, psum, off);
        float mean = psum * (1.f / 72.f);
        float dv0 = h0 - mean, dv1 = h1 - mean, dv2 = h2 - mean;
        float pss = dv0 * dv0 + dv1 * dv1 + ((lane < 8) ? dv2 * dv2 : 0.f);
        #pragma unroll
        for (int off = 16; off; off >>= 1) pss += __shfl_xor_sync(0xffffffffu, pss, off);
        float rstd = rsqrtf(pss * (1.f / 72.f) + 1e-5f);

        size_t row  = (size_t)(b * S_LEN + S0 + r) * INNER;
        size_t zrow = (size_t)(b * S_LEN + S0 + r) * (2 * INNER) + INNER;
        {
            int c = n * 72 + lane;
            float z = g_y[zrow + c];
            float val = dv0 * rstd * nw0 + sk0 * g_xa[row + c];
            g_hs[row + c] = val * (z / (1.f + expf(-z)));
        }
        {
            int c = n * 72 + 32 + lane;
            float z = g_y[zrow + c];
            float val = dv1 * rstd * nw1 + sk1 * g_xa[row + c];
            g_hs[row + c] = val * (z / (1.f + expf(-z)));
        }
        if (lane < 8) {
            int c = n * 72 + 64 + lane;
            float z = g_y[zrow + c];
            float val = dv2 * rstd * nw2 + sk2 * g_xa[row + c];
            g_hs[row + c] = val * (z / (1.f + expf(-z)));
        }
    }
}

// ---------------- launch ----------------
extern "C" void kernel_launch(void* const* d_in, const int* in_sizes, int n_in,
                              void* d_out, int out_size) {
    const float* x           = (const float*)d_in[0];
    const float* proj_up_w   = (const float*)d_in[1];
    const float* q_w         = (const float*)d_in[2];
    const float* k_w         = (const float*)d_in[3];
    const float* v_w         = (const float*)d_in[4];
    const float* conv_w      = (const float*)d_in[5];
    const float* ig_w        = (const float*)d_in[6];
    const float* ig_b        = (const float*)d_in[7];
    const float* fg_w        = (const float*)d_in[8];
    const float* fg_b        = (const float*)d_in[9];
    const float* norm_w      = (const float*)d_in[10];
    const float* skip        = (const float*)d_in[11];
    const float* proj_down_w = (const float*)d_in[12];
    float* out = (float*)d_out;

    float *py, *phs;
    cudaGetSymbolAddress((void**)&py,  g_y);
    cudaGetSymbolAddress((void**)&phs, g_hs);

    // 1) proj_up: g_y[8192,576] = x[8192,192] @ W_up^T
    gemm_tf32<<<dim3(576 / 64, BS_TOT / 128), 256>>>(x, proj_up_w, py, BS_TOT, 2 * INNER, DIMX);

    // 2) depthwise conv 3x3 + silu -> g_xa
    conv_silu_kernel<<<(BS_TOT * INNER + 255) / 256, 256>>>(conv_w);

    // 3) headwise q,k,v
    qkv_kernel<<<(BS_TOT * NHQ + 255) / 256, 256>>>(q_w, k_w, v_w);

    // 4) gates
    gates_kernel<<<BS_TOT / 8, 256>>>(ig_w, ig_b, fg_w, fg_b);

    // 5) scan per (b,n)
    scan_kernel<<<32, S_LEN>>>();

    // 6) attention + LN + skip + silu(z) -> g_hs
    size_t smem = (size_t)(64 * 76 * 2 + 64 * 88 + 64 * 68 + 4 * 64 + 128) * sizeof(float);
    static int attr_set = 0;
    cudaFuncSetAttribute(attn_kernel, cudaFuncAttributeMaxDynamicSharedMemorySize, (int)smem);
    (void)attr_set;
    attn_kernel<<<dim3(16, 32), 256, smem>>>(norm_w, skip);

    // 7) proj_down: out[8192,192] = g_hs @ W_down^T
    gemm_tf32<<<dim3(DIMX / 64, BS_TOT / 128), 256>>>(phs, proj_down_w, out, BS_TOT, DIMX, INNER);
}

// round 3
// speedup vs baseline: 2.7927x; 1.0392x over previous
#include <cuda_runtime.h>
#include <math.h>
#include <stdint.h>

#define S_LEN 1024
#define BATCH 8
#define BS_TOT 8192          // B*S
#define INNER 288
#define DIMX 192
#define NHQ 72
#define NHM 4
#define DHM 72

// ---------------- scratch (static __device__, no allocations) ----------------
__device__ float g_y [BS_TOT * 2 * INNER];  // proj_up output [8192,576]: x_m | z
__device__ float g_xa[BS_TOT * INNER];      // silu(conv(x_m))
__device__ float g_q [BS_TOT * INNER];
__device__ float g_k [BS_TOT * INNER];
__device__ float g_v [BS_TOT * INNER];
__device__ float g_ig[32 * S_LEN];          // [b*4+n][s]
__device__ float g_fg[32 * S_LEN];
__device__ float g_m [32 * S_LEN];          // ig - lfc
__device__ float g_Mx[32 * S_LEN];          // prefix max of m
__device__ float g_d0[32 * S_LEN];          // exp(-lfc - M)
__device__ float g_hs[BS_TOT * INNER];      // h_state (pre proj_down)

// ---------------- tf32 helpers ----------------
__device__ __forceinline__ float to_tf32(float x) {
    float y;
    asm("cvt.rna.tf32.f32 %0, %1;" : "=f"(y) : "f"(x));
    return y;
}

__device__ __forceinline__ void mma_tf32(float c[4], uint32_t a0, uint32_t a1,
                                         uint32_t a2, uint32_t a3,
                                         uint32_t b0, uint32_t b1) {
    asm volatile(
        "mma.sync.aligned.m16n8k8.row.col.f32.tf32.tf32.f32 "
        "{%0,%1,%2,%3}, {%4,%5,%6,%7}, {%8,%9}, {%0,%1,%2,%3};"
        : "+f"(c[0]), "+f"(c[1]), "+f"(c[2]), "+f"(c[3])
        : "r"(a0), "r"(a1), "r"(a2), "r"(a3), "r"(b0), "r"(b1));
}

// ---------------- tf32 GEMM: C[M,N] = A[M,K] @ B[N,K]^T ----------------
// BM=128, BN=64, BK=32, 256 threads, warps 2(M)x4(N), warp tile 64x16
// register-prefetch double buffering over K tiles
__global__ void __launch_bounds__(256) gemm_tf32(
        const float* __restrict__ A, const float* __restrict__ Bm,
        float* __restrict__ C, int M, int N, int K) {
    __shared__ float As[128][36];
    __shared__ float Bs[64][36];
    int r0 = blockIdx.y * 128, c0 = blockIdx.x * 64;
    int tid = threadIdx.x, lane = tid & 31, warp = tid >> 5;
    int wm = warp >> 2, wn = warp & 3;
    int mb = wm * 64, nb = wn * 16;
    int ln4 = lane >> 2, q4 = lane & 3;
    float acc[4][2][4] = {};

    // load indices: A -> row ra (2 threads/row, 4 f4 each), B -> row rb (4 threads/row, 2 f4 each)
    int ra = tid >> 1, fa = (tid & 1) * 4;          // f4 indices fa..fa+3
    int rb = tid >> 2, fb = (tid & 3) * 2;          // f4 indices fb..fb+1

    int KT = K >> 5;
    float4 pa[4], pb[2];

    // prime tile 0
    #pragma unroll
    for (int u = 0; u < 4; u++)
        pa[u] = *(const float4*)&A[(size_t)(r0 + ra) * K + (fa + u) * 4];
    #pragma unroll
    for (int u = 0; u < 2; u++)
        pb[u] = *(const float4*)&Bm[(size_t)(c0 + rb) * K + (fb + u) * 4];
    #pragma unroll
    for (int u = 0; u < 4; u++) {
        int kk = (fa + u) * 4;
        As[ra][kk + 0] = to_tf32(pa[u].x); As[ra][kk + 1] = to_tf32(pa[u].y);
        As[ra][kk + 2] = to_tf32(pa[u].z); As[ra][kk + 3] = to_tf32(pa[u].w);
    }
    #pragma unroll
    for (int u = 0; u < 2; u++) {
        int kk = (fb + u) * 4;
        Bs[rb][kk + 0] = to_tf32(pb[u].x); Bs[rb][kk + 1] = to_tf32(pb[u].y);
        Bs[rb][kk + 2] = to_tf32(pb[u].z); Bs[rb][kk + 3] = to_tf32(pb[u].w);
    }
    __syncthreads();

    for (int kt = 0; kt < KT; kt++) {
        // prefetch next K tile into regs
        if (kt + 1 < KT) {
            int k0 = (kt + 1) * 32;
            #pragma unroll
            for (int u = 0; u < 4; u++)
                pa[u] = *(const float4*)&A[(size_t)(r0 + ra) * K + k0 + (fa + u) * 4];
            #pragma unroll
            for (int u = 0; u < 2; u++)
                pb[u] = *(const float4*)&Bm[(size_t)(c0 + rb) * K + k0 + (fb + u) * 4];
        }
        // compute on current smem tile
        #pragma unroll
        for (int ks = 0; ks < 32; ks += 8) {
            uint32_t a[4][4];
            #pragma unroll
            for (int mf = 0; mf < 4; mf++) {
                int m0 = mb + mf * 16;
                a[mf][0] = __float_as_uint(As[m0 + ln4][ks + q4]);
                a[mf][1] = __float_as_uint(As[m0 + 8 + ln4][ks + q4]);
                a[mf][2] = __float_as_uint(As[m0 + ln4][ks + 4 + q4]);
                a[mf][3] = __float_as_uint(As[m0 + 8 + ln4][ks + 4 + q4]);
            }
            #pragma unroll
            for (int nf = 0; nf < 2; nf++) {
                int n0 = nb + nf * 8;
                uint32_t b0 = __float_as_uint(Bs[n0 + ln4][ks + q4]);
                uint32_t b1 = __float_as_uint(Bs[n0 + ln4][ks + 4 + q4]);
                #pragma unroll
                for (int mf = 0; mf < 4; mf++)
                    mma_tf32(acc[mf][nf], a[mf][0], a[mf][1], a[mf][2], a[mf][3], b0, b1);
            }
        }
        __syncthreads();
        if (kt + 1 < KT) {
            #pragma unroll
            for (int u = 0; u < 4; u++) {
                int kk = (fa + u) * 4;
                As[ra][kk + 0] = to_tf32(pa[u].x); As[ra][kk + 1] = to_tf32(pa[u].y);
                As[ra][kk + 2] = to_tf32(pa[u].z); As[ra][kk + 3] = to_tf32(pa[u].w);
            }
            #pragma unroll
            for (int u = 0; u < 2; u++) {
                int kk = (fb + u) * 4;
                Bs[rb][kk + 0] = to_tf32(pb[u].x); Bs[rb][kk + 1] = to_tf32(pb[u].y);
                Bs[rb][kk + 2] = to_tf32(pb[u].z); Bs[rb][kk + 3] = to_tf32(pb[u].w);
            }
            __syncthreads();
        }
    }

    #pragma unroll
    for (int mf = 0; mf < 4; mf++)
        #pragma unroll
        for (int nf = 0; nf < 2; nf++) {
            int row = r0 + mb + mf * 16 + ln4;
            int col = c0 + nb + nf * 8 + 2 * q4;
            C[(size_t)row * N + col]       = acc[mf][nf][0];
            C[(size_t)row * N + col + 1]   = acc[mf][nf][1];
            C[(size_t)(row + 8) * N + col]     = acc[mf][nf][2];
            C[(size_t)(row + 8) * N + col + 1] = acc[mf][nf][3];
        }
}

// ---------------- depthwise 3x3 conv (SAME) + SiLU, float4 over channels ----------------
__global__ void conv_silu_kernel(const float* __restrict__ cw) {
    int idx = blockIdx.x * 256 + threadIdx.x;
    if (idx >= BS_TOT * (INNER / 4)) return;
    int c4 = idx % (INNER / 4);
    int bs = idx / (INNER / 4);
    int c = c4 * 4;
    int hw = bs & 1023, b = bs >> 10;
    int h = hw >> 5, w = hw & 31;
    float4 acc = make_float4(0.f, 0.f, 0.f, 0.f);
    #pragma unroll
    for (int dh = -1; dh <= 1; dh++) {
        int hh = h + dh;
        if ((unsigned)hh >= 32u) continue;
        #pragma unroll
        for (int dw = -1; dw <= 1; dw++) {
            int ww = w + dw;
            if ((unsigned)ww >= 32u) continue;
            float4 xv = *(const float4*)&g_y[(size_t)(b * S_LEN + hh * 32 + ww) * (2 * INNER) + c];
            float4 wv = *(const float4*)&cw[((dh + 1) * 3 + (dw + 1)) * INNER + c];
            acc.x += xv.x * wv.x; acc.y += xv.y * wv.y;
            acc.z += xv.z * wv.z; acc.w += xv.w * wv.w;
        }
    }
    acc.x = acc.x / (1.f + expf(-acc.x));
    acc.y = acc.y / (1.f + expf(-acc.y));
    acc.z = acc.z / (1.f + expf(-acc.z));
    acc.w = acc.w / (1.f + expf(-acc.w));
    *(float4*)&g_xa[(size_t)bs * INNER + c] = acc;
}

// ---------------- per-head 4x4 q/k/v transforms ----------------
__global__ void qkv_kernel(const float* __restrict__ qw, const float* __restrict__ kw,
                           const float* __restrict__ vw) {
    __shared__ float swq[NHQ * 16], swk[NHQ * 16], swv[NHQ * 16];
    for (int i = threadIdx.x; i < NHQ * 16; i += 256) {
        swq[i] = qw[i]; swk[i] = kw[i]; swv[i] = vw[i];
    }
    __syncthreads();
    int gid = blockIdx.x * 256 + threadIdx.x;
    if (gid >= BS_TOT * NHQ) return;
    int h = gid % NHQ, bs = gid / NHQ;
    float4 xa = *(const float4*)&g_xa[(size_t)bs * INNER + h * 4];
    float4 xm = *(const float4*)&g_y[(size_t)bs * (2 * INNER) + h * 4];
    float qo[4], ko[4], vo[4];
    #pragma unroll
    for (int o = 0; o < 4; o++) {
        const float* wq = &swq[h * 16 + o * 4];
        const float* wk = &swk[h * 16 + o * 4];
        const float* wv = &swv[h * 16 + o * 4];
        qo[o] = xa.x * wq[0] + xa.y * wq[1] + xa.z * wq[2] + xa.w * wq[3];
        ko[o] = xa.x * wk[0] + xa.y * wk[1] + xa.z * wk[2] + xa.w * wk[3];
        vo[o] = xm.x * wv[0] + xm.y * wv[1] + xm.z * wv[2] + xm.w * wv[3];
    }
    *(float4*)&g_q[(size_t)bs * INNER + h * 4] = make_float4(qo[0], qo[1], qo[2], qo[3]);
    *(float4*)&g_k[(size_t)bs * INNER + h * 4] = make_float4(ko[0], ko[1], ko[2], ko[3]);
    *(float4*)&g_v[(size_t)bs * INNER + h * 4] = make_float4(vo[0], vo[1], vo[2], vo[3]);
}

// ---------------- gate projections: ig/fg [B,4,S], float4 vectorized ----------------
__global__ void gates_kernel(const float* __restrict__ igw, const float* __restrict__ igb,
                             const float* __restrict__ fgw, const float* __restrict__ fgb) {
    __shared__ float4 sig4[NHM * 216], sfg4[NHM * 216];
    for (int i = threadIdx.x; i < NHM * 216; i += 256) {
        sig4[i] = ((const float4*)igw)[i];
        sfg4[i] = ((const float4*)fgw)[i];
    }
    __syncthreads();
    int warp = threadIdx.x >> 5, lane = threadIdx.x & 31;
    int bs = blockIdx.x * 8 + warp;
    float ai[4] = {0, 0, 0, 0}, af[4] = {0, 0, 0, 0};

    #pragma unroll
    for (int arr = 0; arr < 3; arr++) {
        const float4* gp = (const float4*)((arr == 0 ? g_q : arr == 1 ? g_k : g_v)
                                           + (size_t)bs * INNER);
        int cb = arr * 72;
        #pragma unroll
        for (int part = 0; part < 3; part++) {
            int j = part * 32 + lane;
            if (part == 2 && lane >= 8) break;
            float4 g = gp[j];
            int c4 = cb + j;
            #pragma unroll
            for (int n = 0; n < 4; n++) {
                float4 wi = sig4[n * 216 + c4];
                float4 wf = sfg4[n * 216 + c4];
                ai[n] += g.x * wi.x + g.y * wi.y + g.z * wi.z + g.w * wi.w;
                af[n] += g.x * wf.x + g.y * wf.y + g.z * wf.z + g.w * wf.w;
            }
        }
    }
    #pragma unroll
    for (int off = 16; off; off >>= 1) {
        #pragma unroll
        for (int n = 0; n < 4; n++) {
            ai[n] += __shfl_xor_sync(0xffffffffu, ai[n], off);
            af[n] += __shfl_xor_sync(0xffffffffu, af[n], off);
        }
    }
    if (lane == 0) {
        int b = bs >> 10, s = bs & 1023;
        #pragma unroll
        for (int n = 0; n < 4; n++) {
            g_ig[(size_t)(b * 4 + n) * S_LEN + s] = ai[n] + igb[n];
            g_fg[(size_t)(b * 4 + n) * S_LEN + s] = af[n] + fgb[n];
        }
    }
}

// ---------------- scan: lfc (cumsum log_sigmoid fg), m, prefix-max M, d0 ----------------
__global__ void scan_kernel() {
    __shared__ float wbuf[32];
    int t = threadIdx.x, lane = t & 31, wid = t >> 5;
    int base = blockIdx.x * S_LEN;
    float fgv = g_fg[base + t];
    float lf = fminf(fgv, 0.f) - log1pf(expf(-fabsf(fgv)));   // log_sigmoid
    float v = lf;
    #pragma unroll
    for (int o = 1; o < 32; o <<= 1) {
        float u = __shfl_up_sync(0xffffffffu, v, o);
        if (lane >= o) v += u;
    }
    if (lane == 31) wbuf[wid] = v;
    __syncthreads();
    if (wid == 0) {
        float s = wbuf[lane];
        #pragma unroll
        for (int o = 1; o < 32; o <<= 1) {
            float u = __shfl_up_sync(0xffffffffu, s, o);
            if (lane >= o) s += u;
        }
        wbuf[lane] = s;
    }
    __syncthreads();
    float lfc = v + (wid ? wbuf[wid - 1] : 0.f);
    float m = g_ig[base + t] - lfc;
    __syncthreads();
    float mx = m;
    #pragma unroll
    for (int o = 1; o < 32; o <<= 1) {
        float u = __shfl_up_sync(0xffffffffu, mx, o);
        if (lane >= o) mx = fmaxf(mx, u);
    }
    if (lane == 31) wbuf[wid] = mx;
    __syncthreads();
    if (wid == 0) {
        float s = wbuf[lane];
        #pragma unroll
        for (int o = 1; o < 32; o <<= 1) {
            float u = __shfl_up_sync(0xffffffffu, s, o);
            if (lane >= o) s = fmaxf(s, u);
        }
        wbuf[lane] = s;
    }
    __syncthreads();
    float Mv = wid ? fmaxf(mx, wbuf[wid - 1]) : mx;
    g_m [base + t] = m;
    g_Mx[base + t] = Mv;
    g_d0[base + t] = expf(-lfc - Mv);
}

// ---------------- mLSTM attention (tf32 mma) + fused LN/skip/silu(z) ----------------
// grid: (16 row-tiles heavy-first, 32 bn), 256 threads
__global__ void __launch_bounds__(256) attn_kernel(const float* __restrict__ normw,
                                                   const float* __restrict__ skipw) {
    extern __shared__ float sm[];
    float* Qs  = sm;                  // 64*76 (later aliased as O output)
    float* Ks  = Qs + 64 * 76;        // 64*76
    float* Vs  = Ks + 64 * 76;        // 64*88 (cols 72..79 zero pad)
    float* Ps  = Vs + 64 * 88;        // 64*68
    float* wms = Ps + 64 * 68;        // 64
    float* wr  = wms + 64;            // 64
    float* d0s = wr + 64;             // 64
    float* invs = d0s + 64;           // 64
    float* rsA = invs + 64;           // 2*64

    int R  = gridDim.x - 1 - blockIdx.x;   // heavy blocks first
    int bn = blockIdx.y;
    int b = bn >> 2, n = bn & 3;
    int S0 = R * 64;
    int tid = threadIdx.x, lane = tid & 31, warp = tid >> 5;
    int wm = warp >> 1, wn = warp & 1;     // 4(M) x 2(N)
    int ln4 = lane >> 2, q4 = lane & 3;
    int r0 = wm * 16;
    const float scale = 0.11785113019775793f;  // 1/sqrt(72)

    // preload Q tile (as tf32)
    for (int i = tid; i < 64 * 18; i += 256) {
        int r = i / 18, j = (i % 18) * 4;
        float4 v = *(const float4*)&g_q[(size_t)(b * S_LEN + S0 + r) * INNER + n * 72 + j];
        Qs[r * 76 + j + 0] = to_tf32(v.x); Qs[r * 76 + j + 1] = to_tf32(v.y);
        Qs[r * 76 + j + 2] = to_tf32(v.z); Qs[r * 76 + j + 3] = to_tf32(v.w);
    }
    if (tid < 64) {
        float Mv = g_Mx[(size_t)bn * S_LEN + S0 + tid];
        wr[tid]  = expf(-Mv);
        d0s[tid] = g_d0[(size_t)bn * S_LEN + S0 + tid];
        rsA[tid] = 0.f; rsA[64 + tid] = 0.f;
    }
    // zero V pad columns (written once, never overwritten)
    for (int i = tid; i < 64 * 8; i += 256) {
        int r = i >> 3, c = 72 + (i & 7);
        Vs[r * 88 + c] = 0.f;
    }
    __syncthreads();

    // hoist Q fragments (tile-invariant across ct loop): 9 k-steps x 4 regs
    uint32_t qf[9][4];
    #pragma unroll
    for (int s = 0; s < 9; s++) {
        int ks = s * 8;
        qf[s][0] = __float_as_uint(Qs[(r0 + ln4) * 76 + ks + q4]);
        qf[s][1] = __float_as_uint(Qs[(r0 + 8 + ln4) * 76 + ks + q4]);
        qf[s][2] = __float_as_uint(Qs[(r0 + ln4) * 76 + ks + 4 + q4]);
        qf[s][3] = __float_as_uint(Qs[(r0 + 8 + ln4) * 76 + ks + 4 + q4]);
    }

    float o[5][4] = {};   // persistent PV accumulators (16x40 per warp)

    for (int ct = 0; ct <= R; ct++) {
        __syncthreads();   // prev Phase B done before overwriting K/V/wm
        int T0 = ct * 64;
        for (int i = tid; i < 64 * 18; i += 256) {
            int r = i / 18, j = (i % 18) * 4;
            size_t gb = (size_t)(b * S_LEN + T0 + r) * INNER + n * 72 + j;
            float4 kv = *(const float4*)&g_k[gb];
            float4 vv = *(const float4*)&g_v[gb];
            Ks[r * 76 + j + 0] = to_tf32(kv.x); Ks[r * 76 + j + 1] = to_tf32(kv.y);
            Ks[r * 76 + j + 2] = to_tf32(kv.z); Ks[r * 76 + j + 3] = to_tf32(kv.w);
            Vs[r * 88 + j + 0] = to_tf32(vv.x); Vs[r * 88 + j + 1] = to_tf32(vv.y);
            Vs[r * 88 + j + 2] = to_tf32(vv.z); Vs[r * 88 + j + 3] = to_tf32(vv.w);
        }
        if (tid < 64) wms[tid] = expf(g_m[(size_t)bn * S_LEN + T0 + tid]);
        __syncthreads();

        // ---- Phase A: P = Q @ K^T  (64x64x72) ----
        float pc[4][4] = {};
        #pragma unroll
        for (int s = 0; s < 9; s++) {
            int ks = s * 8;
            #pragma unroll
            for (int nf = 0; nf < 4; nf++) {
                int c0 = wn * 32 + nf * 8;
                uint32_t b0 = __float_as_uint(Ks[(c0 + ln4) * 76 + ks + q4]);
                uint32_t b1 = __float_as_uint(Ks[(c0 + ln4) * 76 + ks + 4 + q4]);
                mma_tf32(pc[nf], qf[s][0], qf[s][1], qf[s][2], qf[s][3], b0, b1);
            }
        }
        // weight, mask, tf32-round, store to Ps, accumulate rowsums
        bool diag = (ct == R);
        int rr = r0 + ln4;
        float w0 = wr[rr] * scale, w1 = wr[rr + 8] * scale;
        float s_r = 0.f, s_r8 = 0.f;
        #pragma unroll
        for (int nf = 0; nf < 4; nf++) {
            int cbase = wn * 32 + nf * 8 + 2 * q4;
            #pragma unroll
            for (int e = 0; e < 2; e++) {
                int c = cbase + e;
                float wc = wms[c];
                float v0 = pc[nf][e]     * w0 * wc;
                float v1 = pc[nf][2 + e] * w1 * wc;
                if (diag && c > rr)     v0 = 0.f;
                if (diag && c > rr + 8) v1 = 0.f;
                v0 = to_tf32(v0); v1 = to_tf32(v1);
                Ps[rr * 68 + c] = v0;
                Ps[(rr + 8) * 68 + c] = v1;
                s_r += v0; s_r8 += v1;
            }
        }
        s_r  += __shfl_xor_sync(0xffffffffu, s_r, 1);
        s_r  += __shfl_xor_sync(0xffffffffu, s_r, 2);
        s_r8 += __shfl_xor_sync(0xffffffffu, s_r8, 1);
        s_r8 += __shfl_xor_sync(0xffffffffu, s_r8, 2);
        if (q4 == 0) {
            rsA[wn * 64 + rr]     += s_r;
            rsA[wn * 64 + rr + 8] += s_r8;
        }
        __syncthreads();

        // ---- Phase B: O += P @ V  (64x80x64) ----
        #pragma unroll
        for (int ks = 0; ks < 64; ks += 8) {
            uint32_t a0 = __float_as_uint(Ps[(r0 + ln4) * 68 + ks + q4]);
            uint32_t a1 = __float_as_uint(Ps[(r0 + 8 + ln4) * 68 + ks + q4]);
            uint32_t a2 = __float_as_uint(Ps[(r0 + ln4) * 68 + ks + 4 + q4]);
            uint32_t a3 = __float_as_uint(Ps[(r0 + 8 + ln4) * 68 + ks + 4 + q4]);
            #pragma unroll
            for (int nf = 0; nf < 5; nf++) {
                int c0 = wn * 40 + nf * 8;
                uint32_t b0 = __float_as_uint(Vs[(ks + q4) * 88 + c0 + ln4]);
                uint32_t b1 = __float_as_uint(Vs[(ks + 4 + q4) * 88 + c0 + ln4]);
                mma_tf32(o[nf], a0, a1, a2, a3, b0, b1);
            }
        }
    }
    __syncthreads();

    // normalizer
    if (tid < 64) {
        float rs = rsA[tid] + rsA[64 + tid];
        float nrm = fmaxf(fabsf(rs), d0s[tid]);
        invs[tid] = 1.f / (nrm + 1e-6f);
    }
    __syncthreads();

    // write normalized O into Qs (reused as O buffer, stride 76, cols 0..71)
    {
        float i0 = invs[r0 + ln4], i1 = invs[r0 + 8 + ln4];
        #pragma unroll
        for (int nf = 0; nf < 5; nf++) {
            int cb = wn * 40 + nf * 8 + 2 * q4;
            if (cb < 72) {
                Qs[(r0 + ln4) * 76 + cb]         = o[nf][0] * i0;
                Qs[(r0 + ln4) * 76 + cb + 1]     = o[nf][1] * i0;
                Qs[(r0 + 8 + ln4) * 76 + cb]     = o[nf][2] * i1;
                Qs[(r0 + 8 + ln4) * 76 + cb + 1] = o[nf][3] * i1;
            }
        }
    }
    __syncthreads();

    // Epilogue: per-row LN + skip + silu(z)  (warp owns 8 rows)
    int re0 = warp * 8;
    float nw0 = normw[n * 72 + lane];
    float sk0 = skipw[n * 72 + lane];
    float nw1 = normw[n * 72 + 32 + lane];
    float sk1 = skipw[n * 72 + 32 + lane];
    float nw2 = 0.f, sk2 = 0.f;
    if (lane < 8) { nw2 = normw[n * 72 + 64 + lane]; sk2 = skipw[n * 72 + 64 + lane]; }

    #pragma unroll
    for (int r8 = 0; r8 < 8; r8++) {
        int r = re0 + r8;
        float h0 = Qs[r * 76 + lane];
        float h1 = Qs[r * 76 + 32 + lane];
        float h2 = (lane < 8) ? Qs[r * 76 + 64 + lane] : 0.f;
        float psum = h0 + h1 + h2;
        #pragma unroll
        for (int off = 16; off; off >>= 1) psum += __shfl_xor_sync(0xffffffffu, psum, off);
        float mean = psum * (1.f / 72.f);
        float dv0 = h0 - mean, dv1 = h1 - mean, dv2 = h2 - mean;
        float pss = dv0 * dv0 + dv1 * dv1 + ((lane < 8) ? dv2 * dv2 : 0.f);
        #pragma unroll
        for (int off = 16; off; off >>= 1) pss += __shfl_xor_sync(0xffffffffu, pss, off);
        float rstd = rsqrtf(pss * (1.f / 72.f) + 1e-5f);

        size_t row  = (size_t)(b * S_LEN + S0 + r) * INNER;
        size_t zrow = (size_t)(b * S_LEN + S0 + r) * (2 * INNER) + INNER;
        {
            int c = n * 72 + lane;
            float z = g_y[zrow + c];
            float val = dv0 * rstd * nw0 + sk0 * g_xa[row + c];
            g_hs[row + c] = val * (z / (1.f + expf(-z)));
        }
        {
            int c = n * 72 + 32 + lane;
            float z = g_y[zrow + c];
            float val = dv1 * rstd * nw1 + sk1 * g_xa[row + c];
            g_hs[row + c] = val * (z / (1.f + expf(-z)));
        }
        if (lane < 8) {
            int c = n * 72 + 64 + lane;
            float z = g_y[zrow + c];
            float val = dv2 * rstd * nw2 + sk2 * g_xa[row + c];
            g_hs[row + c] = val * (z / (1.f + expf(-z)));
        }
    }
}

// ---------------- launch ----------------
extern "C" void kernel_launch(void* const* d_in, const int* in_sizes, int n_in,
                              void* d_out, int out_size) {
    const float* x           = (const float*)d_in[0];
    const float* proj_up_w   = (const float*)d_in[1];
    const float* q_w         = (const float*)d_in[2];
    const float* k_w         = (const float*)d_in[3];
    const float* v_w         = (const float*)d_in[4];
    const float* conv_w      = (const float*)d_in[5];
    const float* ig_w        = (const float*)d_in[6];
    const float* ig_b        = (const float*)d_in[7];
    const float* fg_w        = (const float*)d_in[8];
    const float* fg_b        = (const float*)d_in[9];
    const float* norm_w      = (const float*)d_in[10];
    const float* skip        = (const float*)d_in[11];
    const float* proj_down_w = (const float*)d_in[12];
    float* out = (float*)d_out;

    float *py, *phs;
    cudaGetSymbolAddress((void**)&py,  g_y);
    cudaGetSymbolAddress((void**)&phs, g_hs);

    // 1) proj_up: g_y[8192,576] = x[8192,192] @ W_up^T
    gemm_tf32<<<dim3(576 / 64, BS_TOT / 128), 256>>>(x, proj_up_w, py, BS_TOT, 2 * INNER, DIMX);

    // 2) depthwise conv 3x3 + silu -> g_xa
    conv_silu_kernel<<<(BS_TOT * (INNER / 4) + 255) / 256, 256>>>(conv_w);

    // 3) headwise q,k,v
    qkv_kernel<<<(BS_TOT * NHQ + 255) / 256, 256>>>(q_w, k_w, v_w);

    // 4) gates
    gates_kernel<<<BS_TOT / 8, 256>>>(ig_w, ig_b, fg_w, fg_b);

    // 5) scan per (b,n)
    scan_kernel<<<32, S_LEN>>>();

    // 6) attention + LN + skip + silu(z) -> g_hs
    size_t smem = (size_t)(64 * 76 * 2 + 64 * 88 + 64 * 68 + 4 * 64 + 128) * sizeof(float);
    cudaFuncSetAttribute(attn_kernel, cudaFuncAttributeMaxDynamicSharedMemorySize, (int)smem);
    attn_kernel<<<dim3(16, 32), 256, smem>>>(norm_w, skip);

    // 7) proj_down: out[8192,192] = g_hs @ W_down^T
    gemm_tf32<<<dim3(DIMX / 64, BS_TOT / 128), 256>>>(phs, proj_down_w, out, BS_TOT, DIMX, INNER);
}

// round 4
// speedup vs baseline: 3.0936x; 1.1077x over previous
#include <cuda_runtime.h>
#include <math.h>
#include <stdint.h>

#define S_LEN 1024
#define BATCH 8
#define BS_TOT 8192          // B*S
#define INNER 288
#define DIMX 192
#define NHQ 72
#define NHM 4
#define DHM 72

// ---------------- scratch (static __device__, no allocations) ----------------
__device__ float g_y [BS_TOT * 2 * INNER];  // proj_up output [8192,576]: x_m | z
__device__ float g_xa[BS_TOT * INNER];      // silu(conv(x_m))
__device__ float g_q [BS_TOT * INNER];
__device__ float g_k [BS_TOT * INNER];
__device__ float g_v [BS_TOT * INNER];
__device__ float g_ig[32 * S_LEN];          // [b*4+n][s]
__device__ float g_fg[32 * S_LEN];
__device__ float g_m [32 * S_LEN];          // ig - lfc
__device__ float g_Mx[32 * S_LEN];          // prefix max of m
__device__ float g_d0[32 * S_LEN];          // exp(-lfc - M)
__device__ float g_hs[BS_TOT * INNER];      // h_state (pre proj_down)

// ---------------- tf32 helpers ----------------
__device__ __forceinline__ float to_tf32(float x) {
    float y;
    asm("cvt.rna.tf32.f32 %0, %1;" : "=f"(y) : "f"(x));
    return y;
}

__device__ __forceinline__ void mma_tf32(float c[4], uint32_t a0, uint32_t a1,
                                         uint32_t a2, uint32_t a3,
                                         uint32_t b0, uint32_t b1) {
    asm volatile(
        "mma.sync.aligned.m16n8k8.row.col.f32.tf32.tf32.f32 "
        "{%0,%1,%2,%3}, {%4,%5,%6,%7}, {%8,%9}, {%0,%1,%2,%3};"
        : "+f"(c[0]), "+f"(c[1]), "+f"(c[2]), "+f"(c[3])
        : "r"(a0), "r"(a1), "r"(a2), "r"(a3), "r"(b0), "r"(b1));
}

// ---------------- tf32 GEMM: C[M,N] = A[M,K] @ B[N,K]^T ----------------
// BM x 64 x 32 tiles, 256 threads, warps 2(M)x4(N), register double-buffer over K
template<int BM>
__global__ void __launch_bounds__(256) gemm_tf32(
        const float* __restrict__ A, const float* __restrict__ Bm,
        float* __restrict__ C, int M, int N, int K) {
    constexpr int MF = BM / 32;       // 16-row m-frags per warp
    constexpr int NA = BM * 8 / 256;  // A float4 loads per thread
    __shared__ float As[BM][36];
    __shared__ float Bs[64][36];
    int r0 = blockIdx.y * BM, c0 = blockIdx.x * 64;
    int tid = threadIdx.x, lane = tid & 31, warp = tid >> 5;
    int wm = warp >> 2, wn = warp & 3;
    int mb = wm * (BM / 2), nb = wn * 16;
    int ln4 = lane >> 2, q4 = lane & 3;
    float acc[MF][2][4] = {};
    float4 pa[NA], pb[2];

    int KT = K >> 5;

    // prime tile 0
    #pragma unroll
    for (int u = 0; u < NA; u++) {
        int i = tid + u * 256, r = i >> 3, f = i & 7;
        pa[u] = *(const float4*)&A[(size_t)(r0 + r) * K + f * 4];
    }
    #pragma unroll
    for (int u = 0; u < 2; u++) {
        int i = tid + u * 256, r = i >> 3, f = i & 7;
        pb[u] = *(const float4*)&Bm[(size_t)(c0 + r) * K + f * 4];
    }
    #pragma unroll
    for (int u = 0; u < NA; u++) {
        int i = tid + u * 256, r = i >> 3, kk = (i & 7) * 4;
        As[r][kk + 0] = to_tf32(pa[u].x); As[r][kk + 1] = to_tf32(pa[u].y);
        As[r][kk + 2] = to_tf32(pa[u].z); As[r][kk + 3] = to_tf32(pa[u].w);
    }
    #pragma unroll
    for (int u = 0; u < 2; u++) {
        int i = tid + u * 256, r = i >> 3, kk = (i & 7) * 4;
        Bs[r][kk + 0] = to_tf32(pb[u].x); Bs[r][kk + 1] = to_tf32(pb[u].y);
        Bs[r][kk + 2] = to_tf32(pb[u].z); Bs[r][kk + 3] = to_tf32(pb[u].w);
    }
    __syncthreads();

    for (int kt = 0; kt < KT; kt++) {
        if (kt + 1 < KT) {
            int k0 = (kt + 1) * 32;
            #pragma unroll
            for (int u = 0; u < NA; u++) {
                int i = tid + u * 256, r = i >> 3, f = i & 7;
                pa[u] = *(const float4*)&A[(size_t)(r0 + r) * K + k0 + f * 4];
            }
            #pragma unroll
            for (int u = 0; u < 2; u++) {
                int i = tid + u * 256, r = i >> 3, f = i & 7;
                pb[u] = *(const float4*)&Bm[(size_t)(c0 + r) * K + k0 + f * 4];
            }
        }
        #pragma unroll
        for (int ks = 0; ks < 32; ks += 8) {
            uint32_t a[MF][4];
            #pragma unroll
            for (int mf = 0; mf < MF; mf++) {
                int m0 = mb + mf * 16;
                a[mf][0] = __float_as_uint(As[m0 + ln4][ks + q4]);
                a[mf][1] = __float_as_uint(As[m0 + 8 + ln4][ks + q4]);
                a[mf][2] = __float_as_uint(As[m0 + ln4][ks + 4 + q4]);
                a[mf][3] = __float_as_uint(As[m0 + 8 + ln4][ks + 4 + q4]);
            }
            #pragma unroll
            for (int nf = 0; nf < 2; nf++) {
                int n0 = nb + nf * 8;
                uint32_t b0 = __float_as_uint(Bs[n0 + ln4][ks + q4]);
                uint32_t b1 = __float_as_uint(Bs[n0 + ln4][ks + 4 + q4]);
                #pragma unroll
                for (int mf = 0; mf < MF; mf++)
                    mma_tf32(acc[mf][nf], a[mf][0], a[mf][1], a[mf][2], a[mf][3], b0, b1);
            }
        }
        __syncthreads();
        if (kt + 1 < KT) {
            #pragma unroll
            for (int u = 0; u < NA; u++) {
                int i = tid + u * 256, r = i >> 3, kk = (i & 7) * 4;
                As[r][kk + 0] = to_tf32(pa[u].x); As[r][kk + 1] = to_tf32(pa[u].y);
                As[r][kk + 2] = to_tf32(pa[u].z); As[r][kk + 3] = to_tf32(pa[u].w);
            }
            #pragma unroll
            for (int u = 0; u < 2; u++) {
                int i = tid + u * 256, r = i >> 3, kk = (i & 7) * 4;
                Bs[r][kk + 0] = to_tf32(pb[u].x); Bs[r][kk + 1] = to_tf32(pb[u].y);
                Bs[r][kk + 2] = to_tf32(pb[u].z); Bs[r][kk + 3] = to_tf32(pb[u].w);
            }
            __syncthreads();
        }
    }

    #pragma unroll
    for (int mf = 0; mf < MF; mf++)
        #pragma unroll
        for (int nf = 0; nf < 2; nf++) {
            int row = r0 + mb + mf * 16 + ln4;
            int col = c0 + nb + nf * 8 + 2 * q4;
            C[(size_t)row * N + col]       = acc[mf][nf][0];
            C[(size_t)row * N + col + 1]   = acc[mf][nf][1];
            C[(size_t)(row + 8) * N + col]     = acc[mf][nf][2];
            C[(size_t)(row + 8) * N + col + 1] = acc[mf][nf][3];
        }
}

// ---------------- depthwise 3x3 conv (SAME) + SiLU, float4 over channels ----------------
__global__ void conv_silu_kernel(const float* __restrict__ cw) {
    int idx = blockIdx.x * 256 + threadIdx.x;
    if (idx >= BS_TOT * (INNER / 4)) return;
    int c4 = idx % (INNER / 4);
    int bs = idx / (INNER / 4);
    int c = c4 * 4;
    int hw = bs & 1023, b = bs >> 10;
    int h = hw >> 5, w = hw & 31;
    float4 acc = make_float4(0.f, 0.f, 0.f, 0.f);
    #pragma unroll
    for (int dh = -1; dh <= 1; dh++) {
        int hh = h + dh;
        if ((unsigned)hh >= 32u) continue;
        #pragma unroll
        for (int dw = -1; dw <= 1; dw++) {
            int ww = w + dw;
            if ((unsigned)ww >= 32u) continue;
            float4 xv = *(const float4*)&g_y[(size_t)(b * S_LEN + hh * 32 + ww) * (2 * INNER) + c];
            float4 wv = *(const float4*)&cw[((dh + 1) * 3 + (dw + 1)) * INNER + c];
            acc.x += xv.x * wv.x; acc.y += xv.y * wv.y;
            acc.z += xv.z * wv.z; acc.w += xv.w * wv.w;
        }
    }
    acc.x = acc.x / (1.f + expf(-acc.x));
    acc.y = acc.y / (1.f + expf(-acc.y));
    acc.z = acc.z / (1.f + expf(-acc.z));
    acc.w = acc.w / (1.f + expf(-acc.w));
    *(float4*)&g_xa[(size_t)bs * INNER + c] = acc;
}

// ---------------- fused per-head qkv transform + gate projections ----------------
// block = 8 rows, warp per row; gates consume q/k/v from registers
__global__ void __launch_bounds__(256) qkv_gates_kernel(
        const float* __restrict__ qw, const float* __restrict__ kw,
        const float* __restrict__ vw,
        const float* __restrict__ igw, const float* __restrict__ igb,
        const float* __restrict__ fgw, const float* __restrict__ fgb) {
    __shared__ float swq[NHQ * 16], swk[NHQ * 16], swv[NHQ * 16];
    __shared__ float4 sig4[NHM * 216], sfg4[NHM * 216];
    for (int i = threadIdx.x; i < NHQ * 16; i += 256) {
        swq[i] = qw[i]; swk[i] = kw[i]; swv[i] = vw[i];
    }
    for (int i = threadIdx.x; i < NHM * 216; i += 256) {
        sig4[i] = ((const float4*)igw)[i];
        sfg4[i] = ((const float4*)fgw)[i];
    }
    __syncthreads();

    int warp = threadIdx.x >> 5, lane = threadIdx.x & 31;
    int bs = blockIdx.x * 8 + warp;
    const float4* xaRow = (const float4*)&g_xa[(size_t)bs * INNER];
    const float4* xmRow = (const float4*)&g_y[(size_t)bs * (2 * INNER)];
    float4* qRow = (float4*)&g_q[(size_t)bs * INNER];
    float4* kRow = (float4*)&g_k[(size_t)bs * INNER];
    float4* vRow = (float4*)&g_v[(size_t)bs * INNER];

    float ai[4] = {0, 0, 0, 0}, af[4] = {0, 0, 0, 0};

    #pragma unroll
    for (int pass = 0; pass < 3; pass++) {
        int h = pass * 32 + lane;
        if (pass == 2 && lane >= 8) break;
        float4 xa = xaRow[h];
        float4 xm = xmRow[h];
        float qo[4], ko[4], vo[4];
        #pragma unroll
        for (int o = 0; o < 4; o++) {
            const float* wq = &swq[h * 16 + o * 4];
            const float* wk = &swk[h * 16 + o * 4];
            const float* wv = &swv[h * 16 + o * 4];
            qo[o] = xa.x * wq[0] + xa.y * wq[1] + xa.z * wq[2] + xa.w * wq[3];
            ko[o] = xa.x * wk[0] + xa.y * wk[1] + xa.z * wk[2] + xa.w * wk[3];
            vo[o] = xm.x * wv[0] + xm.y * wv[1] + xm.z * wv[2] + xm.w * wv[3];
        }
        float4 q4 = make_float4(qo[0], qo[1], qo[2], qo[3]);
        float4 k4 = make_float4(ko[0], ko[1], ko[2], ko[3]);
        float4 v4 = make_float4(vo[0], vo[1], vo[2], vo[3]);
        qRow[h] = q4; kRow[h] = k4; vRow[h] = v4;
        #pragma unroll
        for (int n = 0; n < 4; n++) {
            float4 w;
            w = sig4[n * 216 + h];
            ai[n] += q4.x * w.x + q4.y * w.y + q4.z * w.z + q4.w * w.w;
            w = sig4[n * 216 + 72 + h];
            ai[n] += k4.x * w.x + k4.y * w.y + k4.z * w.z + k4.w * w.w;
            w = sig4[n * 216 + 144 + h];
            ai[n] += v4.x * w.x + v4.y * w.y + v4.z * w.z + v4.w * w.w;
            w = sfg4[n * 216 + h];
            af[n] += q4.x * w.x + q4.y * w.y + q4.z * w.z + q4.w * w.w;
            w = sfg4[n * 216 + 72 + h];
            af[n] += k4.x * w.x + k4.y * w.y + k4.z * w.z + k4.w * w.w;
            w = sfg4[n * 216 + 144 + h];
            af[n] += v4.x * w.x + v4.y * w.y + v4.z * w.z + v4.w * w.w;
        }
    }
    #pragma unroll
    for (int off = 16; off; off >>= 1) {
        #pragma unroll
        for (int n = 0; n < 4; n++) {
            ai[n] += __shfl_xor_sync(0xffffffffu, ai[n], off);
            af[n] += __shfl_xor_sync(0xffffffffu, af[n], off);
        }
    }
    if (lane == 0) {
        int b = bs >> 10, s = bs & 1023;
        #pragma unroll
        for (int n = 0; n < 4; n++) {
            g_ig[(size_t)(b * 4 + n) * S_LEN + s] = ai[n] + igb[n];
            g_fg[(size_t)(b * 4 + n) * S_LEN + s] = af[n] + fgb[n];
        }
    }
}

// ---------------- scan: lfc (cumsum log_sigmoid fg), m, prefix-max M, d0 ----------------
__global__ void scan_kernel() {
    __shared__ float wbuf[32];
    int t = threadIdx.x, lane = t & 31, wid = t >> 5;
    int base = blockIdx.x * S_LEN;
    float fgv = g_fg[base + t];
    float lf = fminf(fgv, 0.f) - log1pf(expf(-fabsf(fgv)));   // log_sigmoid
    float v = lf;
    #pragma unroll
    for (int o = 1; o < 32; o <<= 1) {
        float u = __shfl_up_sync(0xffffffffu, v, o);
        if (lane >= o) v += u;
    }
    if (lane == 31) wbuf[wid] = v;
    __syncthreads();
    if (wid == 0) {
        float s = wbuf[lane];
        #pragma unroll
        for (int o = 1; o < 32; o <<= 1) {
            float u = __shfl_up_sync(0xffffffffu, s, o);
            if (lane >= o) s += u;
        }
        wbuf[lane] = s;
    }
    __syncthreads();
    float lfc = v + (wid ? wbuf[wid - 1] : 0.f);
    float m = g_ig[base + t] - lfc;
    __syncthreads();
    float mx = m;
    #pragma unroll
    for (int o = 1; o < 32; o <<= 1) {
        float u = __shfl_up_sync(0xffffffffu, mx, o);
        if (lane >= o) mx = fmaxf(mx, u);
    }
    if (lane == 31) wbuf[wid] = mx;
    __syncthreads();
    if (wid == 0) {
        float s = wbuf[lane];
        #pragma unroll
        for (int o = 1; o < 32; o <<= 1) {
            float u = __shfl_up_sync(0xffffffffu, s, o);
            if (lane >= o) s = fmaxf(s, u);
        }
        wbuf[lane] = s;
    }
    __syncthreads();
    float Mv = wid ? fmaxf(mx, wbuf[wid - 1]) : mx;
    g_m [base + t] = m;
    g_Mx[base + t] = Mv;
    g_d0[base + t] = expf(-lfc - Mv);
}

// ---------------- mLSTM attention v3: register P, 4 warps, shuffle repack ----------------
// grid: (16 row-tiles heavy-first, 32 bn), 128 threads, ~61KB smem -> 3 blocks/SM
__global__ void __launch_bounds__(128) attn_kernel(const float* __restrict__ normw,
                                                   const float* __restrict__ skipw) {
    extern __shared__ float sm[];
    float* Qs  = sm;                  // 64*76 (reused as O buffer)
    float* Ks  = Qs + 64 * 76;        // 64*76
    float* Vs  = Ks + 64 * 76;        // 64*88 (stride 88 for conflict-free B frags)
    float* wms = Vs + 64 * 88;        // 64
    float* wr  = wms + 64;            // 64
    float* d0s = wr + 64;             // 64

    int R  = gridDim.x - 1 - blockIdx.x;   // heavy blocks first
    int bn = blockIdx.y;
    int b = bn >> 2, n = bn & 3;
    int S0 = R * 64;
    int tid = threadIdx.x, lane = tid & 31, warp = tid >> 5;   // 4 warps
    int ln4 = lane >> 2, q4 = lane & 3;
    int r0 = warp * 16;
    const float scale = 0.11785113019775793f;  // 1/sqrt(72)
    const unsigned FULL = 0xffffffffu;

    // preload Q tile (tf32)
    for (int i = tid; i < 64 * 18; i += 128) {
        int r = i / 18, j = (i % 18) * 4;
        float4 v = *(const float4*)&g_q[(size_t)(b * S_LEN + S0 + r) * INNER + n * 72 + j];
        Qs[r * 76 + j + 0] = to_tf32(v.x); Qs[r * 76 + j + 1] = to_tf32(v.y);
        Qs[r * 76 + j + 2] = to_tf32(v.z); Qs[r * 76 + j + 3] = to_tf32(v.w);
    }
    if (tid < 64) {
        float Mv = g_Mx[(size_t)bn * S_LEN + S0 + tid];
        wr[tid]  = expf(-Mv);
        d0s[tid] = g_d0[(size_t)bn * S_LEN + S0 + tid];
    }
    __syncthreads();

    // hoist Q fragments (rows r0..r0+15, all 72 k)
    uint32_t qf[9][4];
    #pragma unroll
    for (int s = 0; s < 9; s++) {
        int ks = s * 8;
        qf[s][0] = __float_as_uint(Qs[(r0 + ln4) * 76 + ks + q4]);
        qf[s][1] = __float_as_uint(Qs[(r0 + 8 + ln4) * 76 + ks + q4]);
        qf[s][2] = __float_as_uint(Qs[(r0 + ln4) * 76 + ks + 4 + q4]);
        qf[s][3] = __float_as_uint(Qs[(r0 + 8 + ln4) * 76 + ks + 4 + q4]);
    }

    float o[9][4] = {};       // 16 rows x 72 cols per warp
    float rs0 = 0.f, rs1 = 0.f;  // rowsum accumulators (rows r0+ln4, r0+8+ln4)
    int rr = r0 + ln4;
    float w0 = wr[rr] * scale, w1 = wr[rr + 8] * scale;

    int s0l = 4 * ln4 + (q4 >> 1);
    int s1l = s0l + 2;
    bool hi = q4 & 1;

    for (int ct = 0; ct <= R; ct++) {
        __syncthreads();   // prev Phase B done reading Vs
        int T0 = ct * 64;
        for (int i = tid; i < 64 * 18; i += 128) {
            int r = i / 18, j = (i % 18) * 4;
            size_t gb = (size_t)(b * S_LEN + T0 + r) * INNER + n * 72 + j;
            float4 kv = *(const float4*)&g_k[gb];
            float4 vv = *(const float4*)&g_v[gb];
            Ks[r * 76 + j + 0] = to_tf32(kv.x); Ks[r * 76 + j + 1] = to_tf32(kv.y);
            Ks[r * 76 + j + 2] = to_tf32(kv.z); Ks[r * 76 + j + 3] = to_tf32(kv.w);
            Vs[r * 88 + j + 0] = to_tf32(vv.x); Vs[r * 88 + j + 1] = to_tf32(vv.y);
            Vs[r * 88 + j + 2] = to_tf32(vv.z); Vs[r * 88 + j + 3] = to_tf32(vv.w);
        }
        if (tid < 64) wms[tid] = expf(g_m[(size_t)bn * S_LEN + T0 + tid]);
        __syncthreads();

        // ---- Phase A: P(16x64) = Q @ K^T ----
        float pc[8][4] = {};
        #pragma unroll
        for (int s = 0; s < 9; s++) {
            int ks = s * 8;
            #pragma unroll
            for (int nf = 0; nf < 8; nf++) {
                int c0 = nf * 8;
                uint32_t b0 = __float_as_uint(Ks[(c0 + ln4) * 76 + ks + q4]);
                uint32_t b1 = __float_as_uint(Ks[(c0 + ln4) * 76 + ks + 4 + q4]);
                mma_tf32(pc[nf], qf[s][0], qf[s][1], qf[s][2], qf[s][3], b0, b1);
            }
        }
        // weight, mask, tf32-round in registers; accumulate rowsums
        bool diag = (ct == R);
        #pragma unroll
        for (int nf = 0; nf < 8; nf++) {
            #pragma unroll
            for (int e = 0; e < 2; e++) {
                int c = nf * 8 + 2 * q4 + e;
                float wc = wms[c];
                float v0 = pc[nf][e]     * w0 * wc;
                float v1 = pc[nf][2 + e] * w1 * wc;
                if (diag && c > rr)     v0 = 0.f;
                if (diag && c > rr + 8) v1 = 0.f;
                v0 = to_tf32(v0); v1 = to_tf32(v1);
                pc[nf][e]     = v0;
                pc[nf][2 + e] = v1;
                rs0 += v0; rs1 += v1;
            }
        }

        // ---- Phase B: O += P @ V  (16x72x64), P repacked via shuffles ----
        #pragma unroll
        for (int g = 0; g < 8; g++) {
            float x0 = __shfl_sync(FULL, pc[g][0], s0l);
            float x1 = __shfl_sync(FULL, pc[g][1], s0l);
            float y0 = __shfl_sync(FULL, pc[g][0], s1l);
            float y1 = __shfl_sync(FULL, pc[g][1], s1l);
            float u0 = __shfl_sync(FULL, pc[g][2], s0l);
            float u1 = __shfl_sync(FULL, pc[g][3], s0l);
            float t0 = __shfl_sync(FULL, pc[g][2], s1l);
            float t1 = __shfl_sync(FULL, pc[g][3], s1l);
            uint32_t a0 = __float_as_uint(hi ? x1 : x0);
            uint32_t a2 = __float_as_uint(hi ? y1 : y0);
            uint32_t a1 = __float_as_uint(hi ? u1 : u0);
            uint32_t a3 = __float_as_uint(hi ? t1 : t0);
            int kb = g * 8;
            #pragma unroll
            for (int nf = 0; nf < 9; nf++) {
                int c0 = nf * 8;
                uint32_t b0 = __float_as_uint(Vs[(kb + q4) * 88 + c0 + ln4]);
                uint32_t b1 = __float_as_uint(Vs[(kb + 4 + q4) * 88 + c0 + ln4]);
                mma_tf32(o[nf], a0, a1, a2, a3, b0, b1);
            }
        }
    }

    // normalizer (in registers, replicated across quad)
    rs0 += __shfl_xor_sync(FULL, rs0, 1);
    rs0 += __shfl_xor_sync(FULL, rs0, 2);
    rs1 += __shfl_xor_sync(FULL, rs1, 1);
    rs1 += __shfl_xor_sync(FULL, rs1, 2);
    float inv0 = 1.f / (fmaxf(fabsf(rs0), d0s[rr]) + 1e-6f);
    float inv1 = 1.f / (fmaxf(fabsf(rs1), d0s[rr + 8]) + 1e-6f);

    // write normalized O into Qs (stride 76, cols 0..71) — disjoint rows per warp
    #pragma unroll
    for (int nf = 0; nf < 9; nf++) {
        int cb = nf * 8 + 2 * q4;
        Qs[rr * 76 + cb]           = o[nf][0] * inv0;
        Qs[rr * 76 + cb + 1]       = o[nf][1] * inv0;
        Qs[(rr + 8) * 76 + cb]     = o[nf][2] * inv1;
        Qs[(rr + 8) * 76 + cb + 1] = o[nf][3] * inv1;
    }
    __syncthreads();

    // Epilogue: per-row LN + skip + silu(z)  (warp owns 16 rows)
    float nw0 = normw[n * 72 + lane];
    float sk0 = skipw[n * 72 + lane];
    float nw1 = normw[n * 72 + 32 + lane];
    float sk1 = skipw[n * 72 + 32 + lane];
    float nw2 = 0.f, sk2 = 0.f;
    if (lane < 8) { nw2 = normw[n * 72 + 64 + lane]; sk2 = skipw[n * 72 + 64 + lane]; }

    #pragma unroll
    for (int r8 = 0; r8 < 16; r8++) {
        int r = warp * 16 + r8;
        float h0 = Qs[r * 76 + lane];
        float h1 = Qs[r * 76 + 32 + lane];
        float h2 = (lane < 8) ? Qs[r * 76 + 64 + lane] : 0.f;
        float psum = h0 + h1 + h2;
        #pragma unroll
        for (int off = 16; off; off >>= 1) psum += __shfl_xor_sync(FULL, psum, off);
        float mean = psum * (1.f / 72.f);
        float dv0 = h0 - mean, dv1 = h1 - mean, dv2 = h2 - mean;
        float pss = dv0 * dv0 + dv1 * dv1 + ((lane < 8) ? dv2 * dv2 : 0.f);
        #pragma unroll
        for (int off = 16; off; off >>= 1) pss += __shfl_xor_sync(FULL, pss, off);
        float rstd = rsqrtf(pss * (1.f / 72.f) + 1e-5f);

        size_t row  = (size_t)(b * S_LEN + S0 + r) * INNER;
        size_t zrow = (size_t)(b * S_LEN + S0 + r) * (2 * INNER) + INNER;
        {
            int c = n * 72 + lane;
            float z = g_y[zrow + c];
            float val = dv0 * rstd * nw0 + sk0 * g_xa[row + c];
            g_hs[row + c] = val * (z / (1.f + expf(-z)));
        }
        {
            int c = n * 72 + 32 + lane;
            float z = g_y[zrow + c];
            float val = dv1 * rstd * nw1 + sk1 * g_xa[row + c];
            g_hs[row + c] = val * (z / (1.f + expf(-z)));
        }
        if (lane < 8) {
            int c = n * 72 + 64 + lane;
            float z = g_y[zrow + c];
            float val = dv2 * rstd * nw2 + sk2 * g_xa[row + c];
            g_hs[row + c] = val * (z / (1.f + expf(-z)));
        }
    }
}

// ---------------- launch ----------------
extern "C" void kernel_launch(void* const* d_in, const int* in_sizes, int n_in,
                              void* d_out, int out_size) {
    const float* x           = (const float*)d_in[0];
    const float* proj_up_w   = (const float*)d_in[1];
    const float* q_w         = (const float*)d_in[2];
    const float* k_w         = (const float*)d_in[3];
    const float* v_w         = (const float*)d_in[4];
    const float* conv_w      = (const float*)d_in[5];
    const float* ig_w        = (const float*)d_in[6];
    const float* ig_b        = (const float*)d_in[7];
    const float* fg_w        = (const float*)d_in[8];
    const float* fg_b        = (const float*)d_in[9];
    const float* norm_w      = (const float*)d_in[10];
    const float* skip        = (const float*)d_in[11];
    const float* proj_down_w = (const float*)d_in[12];
    float* out = (float*)d_out;

    float *py, *phs;
    cudaGetSymbolAddress((void**)&py,  g_y);
    cudaGetSymbolAddress((void**)&phs, g_hs);

    // 1) proj_up: g_y[8192,576] = x[8192,192] @ W_up^T
    gemm_tf32<128><<<dim3(576 / 64, BS_TOT / 128), 256>>>(x, proj_up_w, py, BS_TOT, 2 * INNER, DIMX);

    // 2) depthwise conv 3x3 + silu -> g_xa
    conv_silu_kernel<<<(BS_TOT * (INNER / 4) + 255) / 256, 256>>>(conv_w);

    // 3) fused headwise q,k,v + gates
    qkv_gates_kernel<<<BS_TOT / 8, 256>>>(q_w, k_w, v_w, ig_w, ig_b, fg_w, fg_b);

    // 4) scan per (b,n)
    scan_kernel<<<32, S_LEN>>>();

    // 5) attention + LN + skip + silu(z) -> g_hs
    size_t smem = (size_t)(64 * 76 * 2 + 64 * 88 + 3 * 64) * sizeof(float);
    cudaFuncSetAttribute(attn_kernel, cudaFuncAttributeMaxDynamicSharedMemorySize, (int)smem);
    attn_kernel<<<dim3(16, 32), 128, smem>>>(norm_w, skip);

    // 6) proj_down: out[8192,192] = g_hs @ W_down^T
    gemm_tf32<64><<<dim3(DIMX / 64, BS_TOT / 64), 256>>>(phs, proj_down_w, out, BS_TOT, DIMX, INNER);
}